// round 1
// baseline (speedup 1.0000x reference)
#include <cuda_runtime.h>
#include <cuda_bf16.h>
#include <math_constants.h>

// Problem constants
#define BB   2
#define SS   2048
#define DIM  1536
#define NHD  16
#define HD   96
#define NTOK (BB*SS)            // 4096
#define ATT_SCALE 0.10206207261596575f   // 1/sqrt(96)

// Scratch (device globals; allocation-free)
__device__ float g_q[NTOK * DIM];
__device__ float g_k[NTOK * DIM];
__device__ float g_v[NTOK * DIM];
__device__ float g_ao[NTOK * DIM];

// ---------------------------------------------------------------------------
// GEMM: C[m][n] = sum_k A[m][k] * W[n][k]   (A: MxK row-major, W: NxK row-major)
// 128x128 tile, BK=8, 256 threads, 8x8 per thread, register prefetch.
// ---------------------------------------------------------------------------
__global__ void __launch_bounds__(256) gemm_nt_kernel(
    const float* __restrict__ A, const float* __restrict__ W,
    float* __restrict__ C, int M, int N, int K)
{
    __shared__ float As[8][128];
    __shared__ float Bs[8][128];

    const int tid = threadIdx.x;
    const int lr  = tid >> 1;          // 0..127
    const int lc  = (tid & 1) << 2;    // 0 or 4
    const int tx  = tid & 15;
    const int ty  = tid >> 4;

    const int row0 = blockIdx.y * 128;
    const int col0 = blockIdx.x * 128;

    const float* Aptr = A + (size_t)(row0 + lr) * K + lc;
    const float* Wptr = W + (size_t)(col0 + lr) * K + lc;

    float4 av = *(const float4*)Aptr;
    float4 bv = *(const float4*)Wptr;

    float acc[8][8] = {};

    for (int kt = 0; kt < K; kt += 8) {
        As[lc+0][lr] = av.x; As[lc+1][lr] = av.y; As[lc+2][lr] = av.z; As[lc+3][lr] = av.w;
        Bs[lc+0][lr] = bv.x; Bs[lc+1][lr] = bv.y; Bs[lc+2][lr] = bv.z; Bs[lc+3][lr] = bv.w;
        __syncthreads();

        if (kt + 8 < K) {
            av = *(const float4*)(Aptr + kt + 8);
            bv = *(const float4*)(Wptr + kt + 8);
        }

        #pragma unroll
        for (int k = 0; k < 8; k++) {
            float a[8], b[8];
            *(float4*)(a)     = *(const float4*)&As[k][ty*8];
            *(float4*)(a + 4) = *(const float4*)&As[k][ty*8 + 4];
            *(float4*)(b)     = *(const float4*)&Bs[k][tx*8];
            *(float4*)(b + 4) = *(const float4*)&Bs[k][tx*8 + 4];
            #pragma unroll
            for (int i = 0; i < 8; i++)
                #pragma unroll
                for (int j = 0; j < 8; j++)
                    acc[i][j] += a[i] * b[j];
        }
        __syncthreads();
    }

    #pragma unroll
    for (int i = 0; i < 8; i++) {
        float4 v0 = make_float4(acc[i][0], acc[i][1], acc[i][2], acc[i][3]);
        float4 v1 = make_float4(acc[i][4], acc[i][5], acc[i][6], acc[i][7]);
        float* crow = C + (size_t)(row0 + ty*8 + i) * N + col0 + tx*8;
        *(float4*)(crow)     = v0;
        *(float4*)(crow + 4) = v1;
    }
}

// ---------------------------------------------------------------------------
// 3D RoPE applied in-place to q and k.
// idx = ((t*NH + h)*3 + p)*16 + j ;  pair (j, j+16) within 32-wide axis chunk.
// ---------------------------------------------------------------------------
__global__ void __launch_bounds__(256) rope_kernel(
    float* __restrict__ q, float* __restrict__ k, const int* __restrict__ xyz)
{
    int idx = blockIdx.x * 256 + threadIdx.x;          // total 4096*16*3*16
    int j = idx & 15;
    int p = (idx >> 4) % 3;
    int th = idx / 48;
    int h = th & (NHD - 1);
    int t = th >> 4;
    if (t >= NTOK) return;

    float pos = (float)xyz[t * 3 + p];
    float invf = powf(10000.0f, -(float)j * (1.0f / 16.0f));
    float ang = pos * invf;
    float sn, cs;
    sincosf(ang, &sn, &cs);

    int base = t * DIM + h * HD + p * 32 + j;
    float q1 = q[base], q2 = q[base + 16];
    q[base]      = q1 * cs - q2 * sn;
    q[base + 16] = q2 * cs + q1 * sn;
    float k1 = k[base], k2 = k[base + 16];
    k[base]      = k1 * cs - k2 * sn;
    k[base + 16] = k2 * cs + k1 * sn;
}

// ---------------------------------------------------------------------------
// Flash attention (fp32). Block = 64 queries of one (b,h). 256 threads (16x16).
// Q,K in smem transposed d-major [96][64]; V [64][96]; Ss [64][65].
// ---------------------------------------------------------------------------
#define SS_STRIDE 65
#define SMEM_FLOATS (96*64*2 + 64*96 + 64*SS_STRIDE + 64*3)

__global__ void __launch_bounds__(256) attn_kernel(
    const float* __restrict__ q, const float* __restrict__ k,
    const float* __restrict__ v, float* __restrict__ o)
{
    extern __shared__ float sm[];
    float* Qst = sm;                    // [96][64]
    float* Kst = Qst + 96*64;           // [96][64]
    float* Vs  = Kst + 96*64;           // [64][96]
    float* Spv = Vs  + 64*96;           // [64][65]
    float* m_s = Spv + 64*SS_STRIDE;    // [64]
    float* l_s = m_s + 64;              // [64]
    float* sc_s= l_s + 64;              // [64]

    const int tid = threadIdx.x;
    const int tx = tid & 15;
    const int ty = tid >> 4;
    const int qt = blockIdx.x;          // 0..31 query tile within batch
    const int bh = blockIdx.y;          // b*NH + h
    const int b  = bh >> 4;
    const int h  = bh & 15;

    const size_t base_q = ((size_t)(b * SS + qt * 64)) * DIM + h * HD;

    // Load Q transposed: Qst[d][r]
    #pragma unroll
    for (int i = 0; i < 6; i++) {
        int fid = tid + 256 * i;        // 0..1535
        int r = fid / 24, c4 = fid % 24;
        float4 qv = *(const float4*)&q[base_q + (size_t)r * DIM + c4 * 4];
        Qst[(c4*4+0)*64 + r] = qv.x;
        Qst[(c4*4+1)*64 + r] = qv.y;
        Qst[(c4*4+2)*64 + r] = qv.z;
        Qst[(c4*4+3)*64 + r] = qv.w;
    }
    if (tid < 64) { m_s[tid] = -CUDART_INF_F; l_s[tid] = 0.0f; }

    float o_acc[4][6] = {};

    for (int kt = 0; kt < SS / 64; kt++) {
        __syncthreads();   // previous-iter smem consumers done (also covers Q/m/l init)

        const size_t base_k = ((size_t)(b * SS + kt * 64)) * DIM + h * HD;
        #pragma unroll
        for (int i = 0; i < 6; i++) {
            int fid = tid + 256 * i;
            int r = fid / 24, c4 = fid % 24;
            float4 kv = *(const float4*)&k[base_k + (size_t)r * DIM + c4 * 4];
            Kst[(c4*4+0)*64 + r] = kv.x;
            Kst[(c4*4+1)*64 + r] = kv.y;
            Kst[(c4*4+2)*64 + r] = kv.z;
            Kst[(c4*4+3)*64 + r] = kv.w;
            float4 vv = *(const float4*)&v[base_k + (size_t)r * DIM + c4 * 4];
            *(float4*)&Vs[r * 96 + c4 * 4] = vv;
        }
        __syncthreads();

        // Scores: S[ty*4+i][tx*4+j] = sum_d Qst[d][ty*4+i] * Kst[d][tx*4+j]
        float s_acc[4][4] = {};
        #pragma unroll 8
        for (int d = 0; d < 96; d++) {
            float4 a = *(const float4*)&Qst[d * 64 + ty * 4];
            float4 bq = *(const float4*)&Kst[d * 64 + tx * 4];
            float aa[4] = {a.x, a.y, a.z, a.w};
            float bb[4] = {bq.x, bq.y, bq.z, bq.w};
            #pragma unroll
            for (int i = 0; i < 4; i++)
                #pragma unroll
                for (int j = 0; j < 4; j++)
                    s_acc[i][j] += aa[i] * bb[j];
        }
        #pragma unroll
        for (int i = 0; i < 4; i++)
            #pragma unroll
            for (int j = 0; j < 4; j++)
                Spv[(ty*4 + i) * SS_STRIDE + tx*4 + j] = s_acc[i][j] * ATT_SCALE;
        __syncthreads();

        // Online softmax: 4 threads per row
        {
            int row = tid >> 2, g = tid & 3;
            float* srow = &Spv[row * SS_STRIDE + g * 16];
            float mloc = -CUDART_INF_F;
            #pragma unroll
            for (int c = 0; c < 16; c++) mloc = fmaxf(mloc, srow[c]);
            mloc = fmaxf(mloc, __shfl_xor_sync(0xffffffffu, mloc, 1));
            mloc = fmaxf(mloc, __shfl_xor_sync(0xffffffffu, mloc, 2));
            float m_old = m_s[row];
            float m_new = fmaxf(m_old, mloc);
            float psum = 0.0f;
            #pragma unroll
            for (int c = 0; c < 16; c++) {
                float pv = __expf(srow[c] - m_new);
                srow[c] = pv;
                psum += pv;
            }
            psum += __shfl_xor_sync(0xffffffffu, psum, 1);
            psum += __shfl_xor_sync(0xffffffffu, psum, 2);
            if (g == 0) {
                float sc = __expf(m_old - m_new);
                sc_s[row] = sc;
                l_s[row] = l_s[row] * sc + psum;
                m_s[row] = m_new;
            }
        }
        __syncthreads();

        // O += P @ V ; rows ty*4+i, cols tx*6+j
        float sci[4];
        #pragma unroll
        for (int i = 0; i < 4; i++) sci[i] = sc_s[ty*4 + i];
        #pragma unroll
        for (int i = 0; i < 4; i++)
            #pragma unroll
            for (int j = 0; j < 6; j++)
                o_acc[i][j] *= sci[i];

        #pragma unroll 4
        for (int kk = 0; kk < 64; kk++) {
            float sv[4], vv[6];
            #pragma unroll
            for (int i = 0; i < 4; i++) sv[i] = Spv[(ty*4 + i) * SS_STRIDE + kk];
            #pragma unroll
            for (int j = 0; j < 6; j++) vv[j] = Vs[kk * 96 + tx*6 + j];
            #pragma unroll
            for (int i = 0; i < 4; i++)
                #pragma unroll
                for (int j = 0; j < 6; j++)
                    o_acc[i][j] += sv[i] * vv[j];
        }
    }

    // Normalize and write out (layout matches q: [token][h*96 + d])
    #pragma unroll
    for (int i = 0; i < 4; i++) {
        float linv = 1.0f / l_s[ty*4 + i];
        #pragma unroll
        for (int j = 0; j < 6; j++)
            o[base_q + (size_t)(ty*4 + i) * DIM + tx*6 + j] = o_acc[i][j] * linv;
    }
}

// ---------------------------------------------------------------------------
extern "C" void kernel_launch(void* const* d_in, const int* in_sizes, int n_in,
                              void* d_out, int out_size)
{
    const int*   xyz = (const int*)d_in[0];
    const float* h   = (const float*)d_in[1];
    const float* wq  = (const float*)d_in[2];
    const float* wk  = (const float*)d_in[3];
    const float* wv  = (const float*)d_in[4];
    const float* wo  = (const float*)d_in[5];
    float* out = (float*)d_out;

    float *pq, *pk, *pv, *pao;
    cudaGetSymbolAddress((void**)&pq,  g_q);
    cudaGetSymbolAddress((void**)&pk,  g_k);
    cudaGetSymbolAddress((void**)&pv,  g_v);
    cudaGetSymbolAddress((void**)&pao, g_ao);

    dim3 ggrid(DIM / 128, NTOK / 128);   // (12, 32)
    gemm_nt_kernel<<<ggrid, 256>>>(h, wq, pq, NTOK, DIM, DIM);
    gemm_nt_kernel<<<ggrid, 256>>>(h, wk, pk, NTOK, DIM, DIM);
    gemm_nt_kernel<<<ggrid, 256>>>(h, wv, pv, NTOK, DIM, DIM);

    int rope_threads = NTOK * NHD * 3 * 16;
    rope_kernel<<<rope_threads / 256, 256>>>(pq, pk, xyz);

    size_t smem = SMEM_FLOATS * sizeof(float);
    cudaFuncSetAttribute(attn_kernel, cudaFuncAttributeMaxDynamicSharedMemorySize, (int)smem);
    dim3 agrid(SS / 64, BB * NHD);       // (32, 32)
    attn_kernel<<<agrid, 256, smem>>>(pq, pk, pv, pao);

    gemm_nt_kernel<<<ggrid, 256>>>(pao, wo, out, NTOK, DIM, DIM);
}

// round 3
// speedup vs baseline: 1.4374x; 1.4374x over previous
#include <cuda_runtime.h>
#include <cuda_bf16.h>
#include <math_constants.h>
#include <cstdint>

// Problem constants
#define BB   2
#define SS   2048
#define DIM  1536
#define NHD  16
#define HD   96
#define NTOK (BB*SS)            // 4096
#define ATT_SCALE 0.10206207261596575f   // 1/sqrt(96)

// Scratch (device globals; allocation-free)
__device__ float g_q[NTOK * DIM];
__device__ float g_k[NTOK * DIM];
__device__ float g_v[NTOK * DIM];
__device__ float g_ao[NTOK * DIM];

__device__ __nv_bfloat16 g_h_hi[NTOK * DIM],  g_h_lo[NTOK * DIM];
__device__ __nv_bfloat16 g_ao_hi[NTOK * DIM], g_ao_lo[NTOK * DIM];
__device__ __nv_bfloat16 g_wq_hi[DIM * DIM],  g_wq_lo[DIM * DIM];
__device__ __nv_bfloat16 g_wk_hi[DIM * DIM],  g_wk_lo[DIM * DIM];
__device__ __nv_bfloat16 g_wv_hi[DIM * DIM],  g_wv_lo[DIM * DIM];
__device__ __nv_bfloat16 g_wo_hi[DIM * DIM],  g_wo_lo[DIM * DIM];

// ---------------------------------------------------------------------------
// fp32 -> (bf16 hi, bf16 lo) split. n must be multiple of 4.
// ---------------------------------------------------------------------------
__global__ void __launch_bounds__(256) split_bf16_kernel(
    const float4* __restrict__ x, __nv_bfloat162* __restrict__ hi,
    __nv_bfloat162* __restrict__ lo, int n4)
{
    int i = blockIdx.x * 256 + threadIdx.x;
    if (i >= n4) return;
    float4 v = x[i];
    __nv_bfloat16 h0 = __float2bfloat16(v.x);
    __nv_bfloat16 h1 = __float2bfloat16(v.y);
    __nv_bfloat16 h2 = __float2bfloat16(v.z);
    __nv_bfloat16 h3 = __float2bfloat16(v.w);
    __nv_bfloat16 l0 = __float2bfloat16(v.x - __bfloat162float(h0));
    __nv_bfloat16 l1 = __float2bfloat16(v.y - __bfloat162float(h1));
    __nv_bfloat16 l2 = __float2bfloat16(v.z - __bfloat162float(h2));
    __nv_bfloat16 l3 = __float2bfloat16(v.w - __bfloat162float(h3));
    __nv_bfloat162 a; a.x = h0; a.y = h1;
    __nv_bfloat162 b; b.x = h2; b.y = h3;
    __nv_bfloat162 c; c.x = l0; c.y = l1;
    __nv_bfloat162 d; d.x = l2; d.y = l3;
    hi[i*2]   = a; hi[i*2+1] = b;
    lo[i*2]   = c; lo[i*2+1] = d;
}

// ---------------------------------------------------------------------------
// Tensor-core GEMM (bf16x3 split): C[m][n] = sum_k A[m][k] * W[n][k]
// Block 128x128, BK=32, 256 threads (8 warps 2x4), warp tile 64x32.
// mma.sync m16n8k16; smem holds mma fragments in padded reg-planes.
// ---------------------------------------------------------------------------
#define MMA_BF16(d, a, b) \
  asm volatile("mma.sync.aligned.m16n8k16.row.col.f32.bf16.bf16.f32 " \
    "{%0,%1,%2,%3}, {%4,%5,%6,%7}, {%8,%9}, {%0,%1,%2,%3};" \
    : "+f"(d[0]), "+f"(d[1]), "+f"(d[2]), "+f"(d[3]) \
    : "r"(a[0]), "r"(a[1]), "r"(a[2]), "r"(a[3]), "r"(b[0]), "r"(b[1]))

__global__ void __launch_bounds__(256, 1) gemm_bf16x3_nt(
    const __nv_bfloat16* __restrict__ Ahi, const __nv_bfloat16* __restrict__ Alo,
    const __nv_bfloat16* __restrict__ Whi, const __nv_bfloat16* __restrict__ Wlo,
    float* __restrict__ C, int M, int N, int K)
{
    // Fragment planes: each plane = 33 uint32 (32 lanes + 1 pad word).
    // A planes: idx p = ((kc*8+mb)*2+hl)*4 + reg          (128 planes)
    // B planes: idx p = 128 + ((kc*16+nb)*2+hl)*2 + reg   (128 planes)
    __shared__ unsigned int sm[256 * 33];

    const int tid  = threadIdx.x;
    const int lane = tid & 31;
    const int wid  = tid >> 5;
    const int warp_m = wid >> 2;     // 0..1
    const int warp_n = wid & 3;      // 0..3
    const int row0 = blockIdx.y * 128;
    const int col0 = blockIdx.x * 128;

    // Producer coords: each thread owns k8-chunk kc8 for rows r and r+64.
    const int kc8 = tid & 3;         // which 8-wide k chunk in BK=32
    const int r   = tid >> 2;        // 0..63
    const int kcp = kc8 >> 1;        // k16 index 0..1
    const int k8  = kc8 & 1;         // high/low 8 within k16

    const __nv_bfloat16* a0h = Ahi + (size_t)(row0 + r)      * K + kc8 * 8;
    const __nv_bfloat16* a1h = Ahi + (size_t)(row0 + r + 64) * K + kc8 * 8;
    const __nv_bfloat16* a0l = Alo + (size_t)(row0 + r)      * K + kc8 * 8;
    const __nv_bfloat16* a1l = Alo + (size_t)(row0 + r + 64) * K + kc8 * 8;
    const __nv_bfloat16* w0h = Whi + (size_t)(col0 + r)      * K + kc8 * 8;
    const __nv_bfloat16* w1h = Whi + (size_t)(col0 + r + 64) * K + kc8 * 8;
    const __nv_bfloat16* w0l = Wlo + (size_t)(col0 + r)      * K + kc8 * 8;
    const __nv_bfloat16* w1l = Wlo + (size_t)(col0 + r + 64) * K + kc8 * 8;

    uint4 pf[8];
    pf[0] = *(const uint4*)a0h;  pf[1] = *(const uint4*)a1h;
    pf[2] = *(const uint4*)a0l;  pf[3] = *(const uint4*)a1l;
    pf[4] = *(const uint4*)w0h;  pf[5] = *(const uint4*)w1h;
    pf[6] = *(const uint4*)w0l;  pf[7] = *(const uint4*)w1l;

    float acc[4][4][4] = {};     // [mbl][nbl][c-reg]

    for (int kt = 0; kt < K; kt += 32) {
        __syncthreads();
        // ---- store A fragments: reg = ((m>>3)&1) + 2*k8, lane = (m&7)*4 + w
        #pragma unroll
        for (int hl = 0; hl < 2; hl++) {
            #pragma unroll
            for (int half = 0; half < 2; half++) {
                int m = r + half * 64;
                int p = ((kcp * 8 + (m >> 4)) * 2 + hl) * 4 + ((m >> 3) & 1) + 2 * k8;
                unsigned int* dst = &sm[p * 33 + (m & 7) * 4];
                uint4 v = pf[hl * 2 + half];
                dst[0] = v.x; dst[1] = v.y; dst[2] = v.z; dst[3] = v.w;
            }
        }
        // ---- store B fragments: reg = k8, lane = (n&7)*4 + w
        #pragma unroll
        for (int hl = 0; hl < 2; hl++) {
            #pragma unroll
            for (int half = 0; half < 2; half++) {
                int n = r + half * 64;
                int p = 128 + ((kcp * 16 + (n >> 3)) * 2 + hl) * 2 + k8;
                unsigned int* dst = &sm[p * 33 + (n & 7) * 4];
                uint4 v = pf[4 + hl * 2 + half];
                dst[0] = v.x; dst[1] = v.y; dst[2] = v.z; dst[3] = v.w;
            }
        }
        __syncthreads();

        if (kt + 32 < K) {
            int o = kt + 32;
            pf[0] = *(const uint4*)(a0h + o);  pf[1] = *(const uint4*)(a1h + o);
            pf[2] = *(const uint4*)(a0l + o);  pf[3] = *(const uint4*)(a1l + o);
            pf[4] = *(const uint4*)(w0h + o);  pf[5] = *(const uint4*)(w1h + o);
            pf[6] = *(const uint4*)(w0l + o);  pf[7] = *(const uint4*)(w1l + o);
        }

        #pragma unroll
        for (int kc = 0; kc < 2; kc++) {
            unsigned int af[4][2][4];
            #pragma unroll
            for (int mbl = 0; mbl < 4; mbl++)
                #pragma unroll
                for (int hl = 0; hl < 2; hl++) {
                    int p = ((kc * 8 + warp_m * 4 + mbl) * 2 + hl) * 4;
                    #pragma unroll
                    for (int rg = 0; rg < 4; rg++)
                        af[mbl][hl][rg] = sm[(p + rg) * 33 + lane];
                }
            unsigned int bf[4][2][2];
            #pragma unroll
            for (int nbl = 0; nbl < 4; nbl++)
                #pragma unroll
                for (int hl = 0; hl < 2; hl++) {
                    int p = 128 + ((kc * 16 + warp_n * 4 + nbl) * 2 + hl) * 2;
                    #pragma unroll
                    for (int rg = 0; rg < 2; rg++)
                        bf[nbl][hl][rg] = sm[(p + rg) * 33 + lane];
                }
            #pragma unroll
            for (int mbl = 0; mbl < 4; mbl++)
                #pragma unroll
                for (int nbl = 0; nbl < 4; nbl++) {
                    MMA_BF16(acc[mbl][nbl], af[mbl][0], bf[nbl][0]);  // hi*hi
                    MMA_BF16(acc[mbl][nbl], af[mbl][0], bf[nbl][1]);  // hi*lo
                    MMA_BF16(acc[mbl][nbl], af[mbl][1], bf[nbl][0]);  // lo*hi
                }
        }
    }

    #pragma unroll
    for (int mbl = 0; mbl < 4; mbl++) {
        int mrow = row0 + warp_m * 64 + mbl * 16 + (lane >> 2);
        #pragma unroll
        for (int nbl = 0; nbl < 4; nbl++) {
            int ncol = col0 + warp_n * 32 + nbl * 8 + (lane & 3) * 2;
            float2 v0 = make_float2(acc[mbl][nbl][0], acc[mbl][nbl][1]);
            float2 v1 = make_float2(acc[mbl][nbl][2], acc[mbl][nbl][3]);
            *(float2*)&C[(size_t)mrow * N + ncol]       = v0;
            *(float2*)&C[(size_t)(mrow + 8) * N + ncol] = v1;
        }
    }
}

// ---------------------------------------------------------------------------
// 3D RoPE applied in-place to q and k.
// ---------------------------------------------------------------------------
__global__ void __launch_bounds__(256) rope_kernel(
    float* __restrict__ q, float* __restrict__ k, const int* __restrict__ xyz)
{
    int idx = blockIdx.x * 256 + threadIdx.x;
    int j = idx & 15;
    int p = (idx >> 4) % 3;
    int th = idx / 48;
    int h = th & (NHD - 1);
    int t = th >> 4;
    if (t >= NTOK) return;

    float pos = (float)xyz[t * 3 + p];
    float invf = powf(10000.0f, -(float)j * (1.0f / 16.0f));
    float ang = pos * invf;
    float sn, cs;
    sincosf(ang, &sn, &cs);

    int base = t * DIM + h * HD + p * 32 + j;
    float q1 = q[base], q2 = q[base + 16];
    q[base]      = q1 * cs - q2 * sn;
    q[base + 16] = q2 * cs + q1 * sn;
    float k1 = k[base], k2 = k[base + 16];
    k[base]      = k1 * cs - k2 * sn;
    k[base + 16] = k2 * cs + k1 * sn;
}

// ---------------------------------------------------------------------------
// f32x2 packed helpers (Blackwell full-rate fp32)
// ---------------------------------------------------------------------------
__device__ __forceinline__ unsigned long long pk2(float x, float y) {
    unsigned long long r;
    asm("mov.b64 %0, {%1, %2};" : "=l"(r) : "f"(x), "f"(y));
    return r;
}
__device__ __forceinline__ float2 upk2(unsigned long long v) {
    float2 r;
    asm("mov.b64 {%0, %1}, %2;" : "=f"(r.x), "=f"(r.y) : "l"(v));
    return r;
}
#define FMA2(d, a, b) asm("fma.rn.f32x2 %0, %1, %2, %0;" : "+l"(d) : "l"(a), "l"(b))
#define MUL2(d, a)    asm("mul.rn.f32x2 %0, %0, %1;"     : "+l"(d) : "l"(a))

// ---------------------------------------------------------------------------
// Flash attention (fp32). Block = 64 queries of one (b,h). 256 threads (16x16).
// ---------------------------------------------------------------------------
#define SS_STRIDE 65
#define SMEM_FLOATS (96*64*2 + 64*96 + 64*SS_STRIDE + 64*3)

__global__ void __launch_bounds__(256) attn_kernel(
    const float* __restrict__ q, const float* __restrict__ k,
    const float* __restrict__ v, float* __restrict__ o)
{
    extern __shared__ float sm[];
    float* Qst = sm;                    // [96][64]
    float* Kst = Qst + 96*64;           // [96][64]
    float* Vs  = Kst + 96*64;           // [64][96]
    float* Spv = Vs  + 64*96;           // [64][65]
    float* m_s = Spv + 64*SS_STRIDE;
    float* l_s = m_s + 64;
    float* sc_s= l_s + 64;

    const int tid = threadIdx.x;
    const int tx = tid & 15;
    const int ty = tid >> 4;
    const int qt = blockIdx.x;
    const int bh = blockIdx.y;
    const int b  = bh >> 4;
    const int h  = bh & 15;

    const size_t base_q = ((size_t)(b * SS + qt * 64)) * DIM + h * HD;

    #pragma unroll
    for (int i = 0; i < 6; i++) {
        int fid = tid + 256 * i;
        int r = fid / 24, c4 = fid % 24;
        float4 qv = *(const float4*)&q[base_q + (size_t)r * DIM + c4 * 4];
        Qst[(c4*4+0)*64 + r] = qv.x;
        Qst[(c4*4+1)*64 + r] = qv.y;
        Qst[(c4*4+2)*64 + r] = qv.z;
        Qst[(c4*4+3)*64 + r] = qv.w;
    }
    if (tid < 64) { m_s[tid] = -CUDART_INF_F; l_s[tid] = 0.0f; }

    unsigned long long oacc2[4][3];
    #pragma unroll
    for (int i = 0; i < 4; i++)
        #pragma unroll
        for (int j = 0; j < 3; j++) oacc2[i][j] = pk2(0.0f, 0.0f);

    for (int kt = 0; kt < SS / 64; kt++) {
        __syncthreads();

        const size_t base_k = ((size_t)(b * SS + kt * 64)) * DIM + h * HD;
        #pragma unroll
        for (int i = 0; i < 6; i++) {
            int fid = tid + 256 * i;
            int r = fid / 24, c4 = fid % 24;
            float4 kv = *(const float4*)&k[base_k + (size_t)r * DIM + c4 * 4];
            Kst[(c4*4+0)*64 + r] = kv.x;
            Kst[(c4*4+1)*64 + r] = kv.y;
            Kst[(c4*4+2)*64 + r] = kv.z;
            Kst[(c4*4+3)*64 + r] = kv.w;
            float4 vv = *(const float4*)&v[base_k + (size_t)r * DIM + c4 * 4];
            *(float4*)&Vs[r * 96 + c4 * 4] = vv;
        }
        __syncthreads();

        // Scores
        float s_acc[4][4] = {};
        #pragma unroll 8
        for (int d = 0; d < 96; d++) {
            float4 a = *(const float4*)&Qst[d * 64 + ty * 4];
            float4 bq = *(const float4*)&Kst[d * 64 + tx * 4];
            float aa[4] = {a.x, a.y, a.z, a.w};
            float bb[4] = {bq.x, bq.y, bq.z, bq.w};
            #pragma unroll
            for (int i = 0; i < 4; i++)
                #pragma unroll
                for (int j = 0; j < 4; j++)
                    s_acc[i][j] += aa[i] * bb[j];
        }
        #pragma unroll
        for (int i = 0; i < 4; i++)
            #pragma unroll
            for (int j = 0; j < 4; j++)
                Spv[(ty*4 + i) * SS_STRIDE + tx*4 + j] = s_acc[i][j] * ATT_SCALE;
        __syncthreads();

        // Online softmax
        {
            int row = tid >> 2, g = tid & 3;
            float* srow = &Spv[row * SS_STRIDE + g * 16];
            float mloc = -CUDART_INF_F;
            #pragma unroll
            for (int c = 0; c < 16; c++) mloc = fmaxf(mloc, srow[c]);
            mloc = fmaxf(mloc, __shfl_xor_sync(0xffffffffu, mloc, 1));
            mloc = fmaxf(mloc, __shfl_xor_sync(0xffffffffu, mloc, 2));
            float m_old = m_s[row];
            float m_new = fmaxf(m_old, mloc);
            float psum = 0.0f;
            #pragma unroll
            for (int c = 0; c < 16; c++) {
                float pv = __expf(srow[c] - m_new);
                srow[c] = pv;
                psum += pv;
            }
            psum += __shfl_xor_sync(0xffffffffu, psum, 1);
            psum += __shfl_xor_sync(0xffffffffu, psum, 2);
            if (g == 0) {
                float sc = __expf(m_old - m_new);
                sc_s[row] = sc;
                l_s[row] = l_s[row] * sc + psum;
                m_s[row] = m_new;
            }
        }
        __syncthreads();

        // O = O*scale + P @ V (packed f32x2)
        #pragma unroll
        for (int i = 0; i < 4; i++) {
            float sc = sc_s[ty*4 + i];
            unsigned long long sc2 = pk2(sc, sc);
            #pragma unroll
            for (int j = 0; j < 3; j++) MUL2(oacc2[i][j], sc2);
        }

        #pragma unroll 4
        for (int kk = 0; kk < 64; kk++) {
            unsigned long long sv2[4];
            #pragma unroll
            for (int i = 0; i < 4; i++) {
                float s = Spv[(ty*4 + i) * SS_STRIDE + kk];
                sv2[i] = pk2(s, s);
            }
            unsigned long long vw[3];
            #pragma unroll
            for (int j = 0; j < 3; j++)
                vw[j] = *reinterpret_cast<const unsigned long long*>(&Vs[kk * 96 + tx*6 + j*2]);
            #pragma unroll
            for (int i = 0; i < 4; i++)
                #pragma unroll
                for (int j = 0; j < 3; j++)
                    FMA2(oacc2[i][j], sv2[i], vw[j]);
        }
    }

    #pragma unroll
    for (int i = 0; i < 4; i++) {
        float linv = 1.0f / l_s[ty*4 + i];
        float* orow = &o[base_q + (size_t)(ty*4 + i) * DIM + tx*6];
        #pragma unroll
        for (int j = 0; j < 3; j++) {
            float2 p2 = upk2(oacc2[i][j]);
            orow[j*2]     = p2.x * linv;
            orow[j*2 + 1] = p2.y * linv;
        }
    }
}

// ---------------------------------------------------------------------------
extern "C" void kernel_launch(void* const* d_in, const int* in_sizes, int n_in,
                              void* d_out, int out_size)
{
    const int*   xyz = (const int*)d_in[0];
    const float* h   = (const float*)d_in[1];
    const float* wq  = (const float*)d_in[2];
    const float* wk  = (const float*)d_in[3];
    const float* wv  = (const float*)d_in[4];
    const float* wo  = (const float*)d_in[5];
    float* out = (float*)d_out;

    float *pq, *pk, *pv, *pao;
    cudaGetSymbolAddress((void**)&pq,  g_q);
    cudaGetSymbolAddress((void**)&pk,  g_k);
    cudaGetSymbolAddress((void**)&pv,  g_v);
    cudaGetSymbolAddress((void**)&pao, g_ao);

    __nv_bfloat16 *hh, *hl, *aoh, *aol;
    __nv_bfloat16 *wqh, *wql, *wkh, *wkl, *wvh, *wvl, *woh, *wol;
    cudaGetSymbolAddress((void**)&hh,  g_h_hi);  cudaGetSymbolAddress((void**)&hl,  g_h_lo);
    cudaGetSymbolAddress((void**)&aoh, g_ao_hi); cudaGetSymbolAddress((void**)&aol, g_ao_lo);
    cudaGetSymbolAddress((void**)&wqh, g_wq_hi); cudaGetSymbolAddress((void**)&wql, g_wq_lo);
    cudaGetSymbolAddress((void**)&wkh, g_wk_hi); cudaGetSymbolAddress((void**)&wkl, g_wk_lo);
    cudaGetSymbolAddress((void**)&wvh, g_wv_hi); cudaGetSymbolAddress((void**)&wvl, g_wv_lo);
    cudaGetSymbolAddress((void**)&woh, g_wo_hi); cudaGetSymbolAddress((void**)&wol, g_wo_lo);

    const int nH4 = NTOK * DIM / 4;      // h / ao elements /4
    const int nW4 = DIM * DIM / 4;
    split_bf16_kernel<<<(nH4 + 255)/256, 256>>>((const float4*)h,  (__nv_bfloat162*)hh,  (__nv_bfloat162*)hl,  nH4);
    split_bf16_kernel<<<(nW4 + 255)/256, 256>>>((const float4*)wq, (__nv_bfloat162*)wqh, (__nv_bfloat162*)wql, nW4);
    split_bf16_kernel<<<(nW4 + 255)/256, 256>>>((const float4*)wk, (__nv_bfloat162*)wkh, (__nv_bfloat162*)wkl, nW4);
    split_bf16_kernel<<<(nW4 + 255)/256, 256>>>((const float4*)wv, (__nv_bfloat162*)wvh, (__nv_bfloat162*)wvl, nW4);
    split_bf16_kernel<<<(nW4 + 255)/256, 256>>>((const float4*)wo, (__nv_bfloat162*)woh, (__nv_bfloat162*)wol, nW4);

    dim3 ggrid(DIM / 128, NTOK / 128);   // (12, 32)
    gemm_bf16x3_nt<<<ggrid, 256>>>(hh, hl, wqh, wql, pq, NTOK, DIM, DIM);
    gemm_bf16x3_nt<<<ggrid, 256>>>(hh, hl, wkh, wkl, pk, NTOK, DIM, DIM);
    gemm_bf16x3_nt<<<ggrid, 256>>>(hh, hl, wvh, wvl, pv, NTOK, DIM, DIM);

    int rope_threads = NTOK * NHD * 3 * 16;
    rope_kernel<<<rope_threads / 256, 256>>>(pq, pk, xyz);

    size_t smem = SMEM_FLOATS * sizeof(float);
    cudaFuncSetAttribute(attn_kernel, cudaFuncAttributeMaxDynamicSharedMemorySize, (int)smem);
    dim3 agrid(SS / 64, BB * NHD);
    attn_kernel<<<agrid, 256, smem>>>(pq, pk, pv, pao);

    split_bf16_kernel<<<(nH4 + 255)/256, 256>>>((const float4*)pao, (__nv_bfloat162*)aoh, (__nv_bfloat162*)aol, nH4);
    gemm_bf16x3_nt<<<ggrid, 256>>>(aoh, aol, woh, wol, out, NTOK, DIM, DIM);
}

// round 4
// speedup vs baseline: 2.7337x; 1.9019x over previous
#include <cuda_runtime.h>
#include <cuda_bf16.h>
#include <math_constants.h>
#include <cstdint>

// Problem constants
#define BB   2
#define SS   2048
#define DIM  1536
#define NHD  16
#define HD   96
#define NTOK (BB*SS)            // 4096
#define ATT_SCALE 0.10206207261596575f   // 1/sqrt(96)

// Scratch (device globals; allocation-free)
__device__ float g_q[NTOK * DIM];
__device__ float g_k[NTOK * DIM];
__device__ float g_v[NTOK * DIM];

__device__ __nv_bfloat16 g_h_hi[NTOK * DIM],  g_h_lo[NTOK * DIM];
__device__ __nv_bfloat16 g_ao_hi[NTOK * DIM], g_ao_lo[NTOK * DIM];
__device__ __nv_bfloat16 g_wq_hi[DIM * DIM],  g_wq_lo[DIM * DIM];
__device__ __nv_bfloat16 g_wk_hi[DIM * DIM],  g_wk_lo[DIM * DIM];
__device__ __nv_bfloat16 g_wv_hi[DIM * DIM],  g_wv_lo[DIM * DIM];
__device__ __nv_bfloat16 g_wo_hi[DIM * DIM],  g_wo_lo[DIM * DIM];

// Post-RoPE bf16 splits (q prescaled by ATT_SCALE), as uint32 bf16x2 words
__device__ unsigned int g_qhi[NTOK * DIM / 2], g_qlo[NTOK * DIM / 2];
__device__ unsigned int g_khi[NTOK * DIM / 2], g_klo[NTOK * DIM / 2];
// V transposed per (b,h): [32][96][2048] bf16 -> words [32][96][1024]
__device__ unsigned int g_vthi[32 * 96 * 1024], g_vtlo[32 * 96 * 1024];

// ---------------------------------------------------------------------------
// helpers
// ---------------------------------------------------------------------------
__device__ __forceinline__ unsigned int pack_bf16x2(float lo, float hi) {
    unsigned int r;
    asm("cvt.rn.bf16x2.f32 %0, %1, %2;" : "=r"(r) : "f"(hi), "f"(lo));
    return r;
}
__device__ __forceinline__ float bf16x2_lo(unsigned int w) {
    return __uint_as_float(w << 16);
}
__device__ __forceinline__ float bf16x2_hi(unsigned int w) {
    return __uint_as_float(w & 0xffff0000u);
}

#define MMA_BF16(d, a, b) \
  asm volatile("mma.sync.aligned.m16n8k16.row.col.f32.bf16.bf16.f32 " \
    "{%0,%1,%2,%3}, {%4,%5,%6,%7}, {%8,%9}, {%0,%1,%2,%3};" \
    : "+f"(d[0]), "+f"(d[1]), "+f"(d[2]), "+f"(d[3]) \
    : "r"(a[0]), "r"(a[1]), "r"(a[2]), "r"(a[3]), "r"(b[0]), "r"(b[1]))

#define CPA16(dst_s, src_g) \
  asm volatile("cp.async.ca.shared.global [%0], [%1], 16;" :: "r"(dst_s), "l"(src_g))
#define CP_COMMIT() asm volatile("cp.async.commit_group;" ::: "memory")
#define CP_WAIT0()  asm volatile("cp.async.wait_group 0;" ::: "memory")

// ---------------------------------------------------------------------------
// fp32 -> (bf16 hi, bf16 lo) split. n multiple of 4.
// ---------------------------------------------------------------------------
__global__ void __launch_bounds__(256) split_bf16_kernel(
    const float4* __restrict__ x, __nv_bfloat162* __restrict__ hi,
    __nv_bfloat162* __restrict__ lo, int n4)
{
    int i = blockIdx.x * 256 + threadIdx.x;
    if (i >= n4) return;
    float4 v = x[i];
    __nv_bfloat16 h0 = __float2bfloat16(v.x);
    __nv_bfloat16 h1 = __float2bfloat16(v.y);
    __nv_bfloat16 h2 = __float2bfloat16(v.z);
    __nv_bfloat16 h3 = __float2bfloat16(v.w);
    __nv_bfloat16 l0 = __float2bfloat16(v.x - __bfloat162float(h0));
    __nv_bfloat16 l1 = __float2bfloat16(v.y - __bfloat162float(h1));
    __nv_bfloat16 l2 = __float2bfloat16(v.z - __bfloat162float(h2));
    __nv_bfloat16 l3 = __float2bfloat16(v.w - __bfloat162float(h3));
    __nv_bfloat162 a; a.x = h0; a.y = h1;
    __nv_bfloat162 b; b.x = h2; b.y = h3;
    __nv_bfloat162 c; c.x = l0; c.y = l1;
    __nv_bfloat162 d; d.x = l2; d.y = l3;
    hi[i*2]   = a; hi[i*2+1] = b;
    lo[i*2]   = c; lo[i*2+1] = d;
}

// ---------------------------------------------------------------------------
// Tensor-core GEMM (bf16x3): unchanged from R3 (passing, 2.2e-5)
// ---------------------------------------------------------------------------
__global__ void __launch_bounds__(256, 1) gemm_bf16x3_nt(
    const __nv_bfloat16* __restrict__ Ahi, const __nv_bfloat16* __restrict__ Alo,
    const __nv_bfloat16* __restrict__ Whi, const __nv_bfloat16* __restrict__ Wlo,
    float* __restrict__ C, int M, int N, int K)
{
    __shared__ unsigned int sm[256 * 33];

    const int tid  = threadIdx.x;
    const int lane = tid & 31;
    const int wid  = tid >> 5;
    const int warp_m = wid >> 2;
    const int warp_n = wid & 3;
    const int row0 = blockIdx.y * 128;
    const int col0 = blockIdx.x * 128;

    const int kc8 = tid & 3;
    const int r   = tid >> 2;
    const int kcp = kc8 >> 1;
    const int k8  = kc8 & 1;

    const __nv_bfloat16* a0h = Ahi + (size_t)(row0 + r)      * K + kc8 * 8;
    const __nv_bfloat16* a1h = Ahi + (size_t)(row0 + r + 64) * K + kc8 * 8;
    const __nv_bfloat16* a0l = Alo + (size_t)(row0 + r)      * K + kc8 * 8;
    const __nv_bfloat16* a1l = Alo + (size_t)(row0 + r + 64) * K + kc8 * 8;
    const __nv_bfloat16* w0h = Whi + (size_t)(col0 + r)      * K + kc8 * 8;
    const __nv_bfloat16* w1h = Whi + (size_t)(col0 + r + 64) * K + kc8 * 8;
    const __nv_bfloat16* w0l = Wlo + (size_t)(col0 + r)      * K + kc8 * 8;
    const __nv_bfloat16* w1l = Wlo + (size_t)(col0 + r + 64) * K + kc8 * 8;

    uint4 pf[8];
    pf[0] = *(const uint4*)a0h;  pf[1] = *(const uint4*)a1h;
    pf[2] = *(const uint4*)a0l;  pf[3] = *(const uint4*)a1l;
    pf[4] = *(const uint4*)w0h;  pf[5] = *(const uint4*)w1h;
    pf[6] = *(const uint4*)w0l;  pf[7] = *(const uint4*)w1l;

    float acc[4][4][4] = {};

    for (int kt = 0; kt < K; kt += 32) {
        __syncthreads();
        #pragma unroll
        for (int hl = 0; hl < 2; hl++) {
            #pragma unroll
            for (int half = 0; half < 2; half++) {
                int m = r + half * 64;
                int p = ((kcp * 8 + (m >> 4)) * 2 + hl) * 4 + ((m >> 3) & 1) + 2 * k8;
                unsigned int* dst = &sm[p * 33 + (m & 7) * 4];
                uint4 v = pf[hl * 2 + half];
                dst[0] = v.x; dst[1] = v.y; dst[2] = v.z; dst[3] = v.w;
            }
        }
        #pragma unroll
        for (int hl = 0; hl < 2; hl++) {
            #pragma unroll
            for (int half = 0; half < 2; half++) {
                int n = r + half * 64;
                int p = 128 + ((kcp * 16 + (n >> 3)) * 2 + hl) * 2 + k8;
                unsigned int* dst = &sm[p * 33 + (n & 7) * 4];
                uint4 v = pf[4 + hl * 2 + half];
                dst[0] = v.x; dst[1] = v.y; dst[2] = v.z; dst[3] = v.w;
            }
        }
        __syncthreads();

        if (kt + 32 < K) {
            int o = kt + 32;
            pf[0] = *(const uint4*)(a0h + o);  pf[1] = *(const uint4*)(a1h + o);
            pf[2] = *(const uint4*)(a0l + o);  pf[3] = *(const uint4*)(a1l + o);
            pf[4] = *(const uint4*)(w0h + o);  pf[5] = *(const uint4*)(w1h + o);
            pf[6] = *(const uint4*)(w0l + o);  pf[7] = *(const uint4*)(w1l + o);
        }

        #pragma unroll
        for (int kc = 0; kc < 2; kc++) {
            unsigned int af[4][2][4];
            #pragma unroll
            for (int mbl = 0; mbl < 4; mbl++)
                #pragma unroll
                for (int hl = 0; hl < 2; hl++) {
                    int p = ((kc * 8 + warp_m * 4 + mbl) * 2 + hl) * 4;
                    #pragma unroll
                    for (int rg = 0; rg < 4; rg++)
                        af[mbl][hl][rg] = sm[(p + rg) * 33 + lane];
                }
            unsigned int bf[4][2][2];
            #pragma unroll
            for (int nbl = 0; nbl < 4; nbl++)
                #pragma unroll
                for (int hl = 0; hl < 2; hl++) {
                    int p = 128 + ((kc * 16 + warp_n * 4 + nbl) * 2 + hl) * 2;
                    #pragma unroll
                    for (int rg = 0; rg < 2; rg++)
                        bf[nbl][hl][rg] = sm[(p + rg) * 33 + lane];
                }
            #pragma unroll
            for (int mbl = 0; mbl < 4; mbl++)
                #pragma unroll
                for (int nbl = 0; nbl < 4; nbl++) {
                    MMA_BF16(acc[mbl][nbl], af[mbl][0], bf[nbl][0]);
                    MMA_BF16(acc[mbl][nbl], af[mbl][0], bf[nbl][1]);
                    MMA_BF16(acc[mbl][nbl], af[mbl][1], bf[nbl][0]);
                }
        }
    }

    #pragma unroll
    for (int mbl = 0; mbl < 4; mbl++) {
        int mrow = row0 + warp_m * 64 + mbl * 16 + (lane >> 2);
        #pragma unroll
        for (int nbl = 0; nbl < 4; nbl++) {
            int ncol = col0 + warp_n * 32 + nbl * 8 + (lane & 3) * 2;
            float2 v0 = make_float2(acc[mbl][nbl][0], acc[mbl][nbl][1]);
            float2 v1 = make_float2(acc[mbl][nbl][2], acc[mbl][nbl][3]);
            *(float2*)&C[(size_t)mrow * N + ncol]       = v0;
            *(float2*)&C[(size_t)(mrow + 8) * N + ncol] = v1;
        }
    }
}

// ---------------------------------------------------------------------------
// RoPE + bf16 split: q,k fp32 -> qhi/qlo/khi/klo bf16x2 words.
// q is prescaled by ATT_SCALE. Thread handles one (tok,h,axis,j2): d pairs
// (p*32+2j2, +1) and (+16,+17).
// ---------------------------------------------------------------------------
__global__ void __launch_bounds__(256) rope_split_kernel(
    const float* __restrict__ q, const float* __restrict__ k,
    const int* __restrict__ xyz,
    unsigned int* __restrict__ qhi, unsigned int* __restrict__ qlo,
    unsigned int* __restrict__ khi, unsigned int* __restrict__ klo)
{
    int idx = blockIdx.x * 256 + threadIdx.x;   // NTOK*16*3*8
    int j2 = idx & 7;
    int p  = (idx >> 3) % 3;
    int th = idx / 24;
    int h  = th & 15;
    int t  = th >> 4;
    if (t >= NTOK) return;

    float pos = (float)xyz[t * 3 + p];
    // inv_freq(j) = 10000^(-j/16) = 2^(-j*log2(1e4)/16)
    const float c = 0.83048202372184058696f;   // log2(10000)/16
    int j0 = 2 * j2;
    float s0, c0, s1, c1;
    sincosf(pos * exp2f(-(float)j0 * c), &s0, &c0);
    sincosf(pos * exp2f(-(float)(j0 + 1) * c), &s1, &c1);

    int base = t * DIM + h * HD + p * 32 + j0;
    int wbase = t * (DIM/2) + h * (HD/2) + p * 16 + j2;

    // ---- q (scaled) ----
    {
        float2 a = *(const float2*)&q[base];
        float2 b = *(const float2*)&q[base + 16];
        float o1x = (a.x * c0 - b.x * s0) * ATT_SCALE;
        float o1y = (a.y * c1 - b.y * s1) * ATT_SCALE;
        float o2x = (b.x * c0 + a.x * s0) * ATT_SCALE;
        float o2y = (b.y * c1 + a.y * s1) * ATT_SCALE;
        unsigned int h1 = pack_bf16x2(o1x, o1y);
        unsigned int h2 = pack_bf16x2(o2x, o2y);
        unsigned int l1 = pack_bf16x2(o1x - bf16x2_lo(h1), o1y - bf16x2_hi(h1));
        unsigned int l2 = pack_bf16x2(o2x - bf16x2_lo(h2), o2y - bf16x2_hi(h2));
        qhi[wbase] = h1; qhi[wbase + 8] = h2;
        qlo[wbase] = l1; qlo[wbase + 8] = l2;
    }
    // ---- k ----
    {
        float2 a = *(const float2*)&k[base];
        float2 b = *(const float2*)&k[base + 16];
        float o1x = a.x * c0 - b.x * s0;
        float o1y = a.y * c1 - b.y * s1;
        float o2x = b.x * c0 + a.x * s0;
        float o2y = b.y * c1 + a.y * s1;
        unsigned int h1 = pack_bf16x2(o1x, o1y);
        unsigned int h2 = pack_bf16x2(o2x, o2y);
        unsigned int l1 = pack_bf16x2(o1x - bf16x2_lo(h1), o1y - bf16x2_hi(h1));
        unsigned int l2 = pack_bf16x2(o2x - bf16x2_lo(h2), o2y - bf16x2_hi(h2));
        khi[wbase] = h1; khi[wbase + 8] = h2;
        klo[wbase] = l1; klo[wbase + 8] = l2;
    }
}

// ---------------------------------------------------------------------------
// V transpose + split: g_v [tok][1536] fp32 -> vt hi/lo [bh][96][1024 words]
// (pairs packed along sequence). Block: one (bh, 64-seq tile), 128 threads.
// ---------------------------------------------------------------------------
__global__ void __launch_bounds__(128) vtrans_kernel(
    const float* __restrict__ v,
    unsigned int* __restrict__ vthi, unsigned int* __restrict__ vtlo)
{
    __shared__ float sm[96 * 65];
    const int tid = threadIdx.x;
    const int bh = blockIdx.y;          // b*16 + h
    const int b = bh >> 4, h = bh & 15;
    const int s0 = blockIdx.x * 64;

    // load 64 rows x 96 cols; thread: row s = tid>>1, half = tid&1 (48 cols)
    {
        int s = tid >> 1, half = tid & 1;
        const float* src = v + (size_t)(b * SS + s0 + s) * DIM + h * HD + half * 48;
        #pragma unroll
        for (int i = 0; i < 12; i++) {
            float4 x = *(const float4*)(src + i * 4);
            int d = half * 48 + i * 4;
            sm[(d + 0) * 65 + s] = x.x;
            sm[(d + 1) * 65 + s] = x.y;
            sm[(d + 2) * 65 + s] = x.z;
            sm[(d + 3) * 65 + s] = x.w;
        }
    }
    __syncthreads();

    // write 96 d x 32 words
    #pragma unroll
    for (int i = 0; i < 24; i++) {
        int w = tid + 128 * i;          // 0..3071
        int d = w >> 5, j = w & 31;
        float f0 = sm[d * 65 + 2 * j];
        float f1 = sm[d * 65 + 2 * j + 1];
        unsigned int hi = pack_bf16x2(f0, f1);
        unsigned int lo = pack_bf16x2(f0 - bf16x2_lo(hi), f1 - bf16x2_hi(hi));
        size_t dst = (size_t)(bh * 96 + d) * 1024 + (s0 >> 1) + j;
        vthi[dst] = hi;
        vtlo[dst] = lo;
    }
}

// ---------------------------------------------------------------------------
// MMA flash attention. Block = 64 queries of one (b,h). 128 threads (4 warps,
// warp w owns rows 16w..16w+15). K/V tiles double-buffered via cp.async.
// Smem word layout per buffer: KHI [64][52], KLO [64][52], VHI [96][36],
// VLO [96][36]  (padded strides -> conflict-free fragment LDS).
// ---------------------------------------------------------------------------
#define AKHI 0
#define AKLO 3328
#define AVHI 6656
#define AVLO 10112
#define ABUF 13568            // words per buffer
#define ATT_SMEM_BYTES (2 * ABUF * 4)

__global__ void __launch_bounds__(128, 2) attn_mma_kernel(
    const unsigned int* __restrict__ qhi, const unsigned int* __restrict__ qlo,
    const unsigned int* __restrict__ khi, const unsigned int* __restrict__ klo,
    const unsigned int* __restrict__ vthi, const unsigned int* __restrict__ vtlo,
    unsigned int* __restrict__ aohi, unsigned int* __restrict__ aolo)
{
    extern __shared__ unsigned int smw[];
    unsigned int sbase;
    asm("{ .reg .u64 t; cvta.to.shared.u64 t, %1; cvt.u32.u64 %0, t; }"
        : "=r"(sbase) : "l"(smw));

    const int tid  = threadIdx.x;
    const int lane = tid & 31;
    const int warp = tid >> 5;
    const int qt = blockIdx.x;
    const int bh = blockIdx.y;
    const int b = bh >> 4, h = bh & 15;
    const int h48 = h * 48;
    const int qrow0 = b * SS + qt * 64;

    // ---- Q fragments (registers, once). A-frag m16k16 layout.
    unsigned int qh[6][4], ql[6][4];
    {
        const unsigned int* qhg = qhi + (size_t)qrow0 * 768 + h48;
        const unsigned int* qlg = qlo + (size_t)qrow0 * 768 + h48;
        int r0 = warp * 16 + (lane >> 2);
        #pragma unroll
        for (int kb = 0; kb < 6; kb++) {
            int w0 = kb * 8 + (lane & 3);
            qh[kb][0] = qhg[(size_t)r0 * 768 + w0];
            qh[kb][1] = qhg[(size_t)(r0 + 8) * 768 + w0];
            qh[kb][2] = qhg[(size_t)r0 * 768 + w0 + 4];
            qh[kb][3] = qhg[(size_t)(r0 + 8) * 768 + w0 + 4];
            ql[kb][0] = qlg[(size_t)r0 * 768 + w0];
            ql[kb][1] = qlg[(size_t)(r0 + 8) * 768 + w0];
            ql[kb][2] = qlg[(size_t)r0 * 768 + w0 + 4];
            ql[kb][3] = qlg[(size_t)(r0 + 8) * 768 + w0 + 4];
        }
    }

    float O[12][4];
    #pragma unroll
    for (int nb = 0; nb < 12; nb++)
        #pragma unroll
        for (int i = 0; i < 4; i++) O[nb][i] = 0.0f;
    float m0 = -CUDART_INF_F, m1 = -CUDART_INF_F, l0 = 0.0f, l1 = 0.0f;

    // producer lambda-ish macro: issue cp.async for key-block kt into buffer bi
    const unsigned int* ksrc[2] = { khi, klo };
    const unsigned int* vsrc[2] = { vthi, vtlo };

#define PREFETCH(bi, ktv)                                                      \
    {                                                                          \
        int ktok = b * SS + (ktv) * 64;                                        \
        _Pragma("unroll")                                                      \
        for (int hl = 0; hl < 2; hl++) {                                       \
            const unsigned int* sk = ksrc[hl];                                 \
            _Pragma("unroll")                                                  \
            for (int i = 0; i < 6; i++) {                                      \
                int cc = tid + 128 * i;                                        \
                int key = cc / 12, j = cc - key * 12;                          \
                unsigned int dw = ((bi) * ABUF + hl * AKLO + key * 52 + j * 4);\
                CPA16(sbase + dw * 4,                                          \
                      sk + (size_t)(ktok + key) * 768 + h48 + j * 4);          \
            }                                                                  \
            const unsigned int* sv = vsrc[hl];                                 \
            _Pragma("unroll")                                                  \
            for (int i = 0; i < 6; i++) {                                      \
                int cc = tid + 128 * i;                                        \
                int d = cc >> 3, j = cc & 7;                                   \
                unsigned int dw = ((bi) * ABUF + AVHI + hl * (AVLO - AVHI)     \
                                   + d * 36 + j * 4);                          \
                CPA16(sbase + dw * 4,                                          \
                      sv + (size_t)(bh * 96 + d) * 1024 + (ktv) * 32 + j * 4); \
            }                                                                  \
        }                                                                      \
        CP_COMMIT();                                                           \
    }

    PREFETCH(0, 0);

    for (int kt = 0; kt < SS / 64; kt++) {
        CP_WAIT0();
        __syncthreads();
        if (kt + 1 < SS / 64) PREFETCH((kt + 1) & 1, kt + 1);

        const unsigned int* kh = smw + (kt & 1) * ABUF + AKHI;
        const unsigned int* kl = smw + (kt & 1) * ABUF + AKLO;
        const unsigned int* vh = smw + (kt & 1) * ABUF + AVHI;
        const unsigned int* vl = smw + (kt & 1) * ABUF + AVLO;

        // ---- scores S = Q K^T (scale folded into Q)
        float S[8][4];
        #pragma unroll
        for (int nb = 0; nb < 8; nb++) {
            #pragma unroll
            for (int i = 0; i < 4; i++) S[nb][i] = 0.0f;
            int key = nb * 8 + (lane >> 2);
            #pragma unroll
            for (int kb = 0; kb < 6; kb++) {
                int w0 = kb * 8 + (lane & 3);
                unsigned int bhf[2] = { kh[key * 52 + w0], kh[key * 52 + w0 + 4] };
                unsigned int blf[2] = { kl[key * 52 + w0], kl[key * 52 + w0 + 4] };
                MMA_BF16(S[nb], qh[kb], bhf);
                MMA_BF16(S[nb], qh[kb], blf);
                MMA_BF16(S[nb], ql[kb], bhf);
            }
        }

        // ---- online softmax (rows r=lane>>2 and r+8 within warp tile)
        float ml0 = -CUDART_INF_F, ml1 = -CUDART_INF_F;
        #pragma unroll
        for (int nb = 0; nb < 8; nb++) {
            ml0 = fmaxf(ml0, fmaxf(S[nb][0], S[nb][1]));
            ml1 = fmaxf(ml1, fmaxf(S[nb][2], S[nb][3]));
        }
        ml0 = fmaxf(ml0, __shfl_xor_sync(0xffffffffu, ml0, 1));
        ml0 = fmaxf(ml0, __shfl_xor_sync(0xffffffffu, ml0, 2));
        ml1 = fmaxf(ml1, __shfl_xor_sync(0xffffffffu, ml1, 1));
        ml1 = fmaxf(ml1, __shfl_xor_sync(0xffffffffu, ml1, 2));
        float mn0 = fmaxf(m0, ml0), mn1 = fmaxf(m1, ml1);
        float sc0 = __expf(m0 - mn0), sc1 = __expf(m1 - mn1);
        float r0 = 0.0f, r1 = 0.0f;
        #pragma unroll
        for (int nb = 0; nb < 8; nb++) {
            S[nb][0] = __expf(S[nb][0] - mn0);
            S[nb][1] = __expf(S[nb][1] - mn0);
            S[nb][2] = __expf(S[nb][2] - mn1);
            S[nb][3] = __expf(S[nb][3] - mn1);
            r0 += S[nb][0] + S[nb][1];
            r1 += S[nb][2] + S[nb][3];
        }
        r0 += __shfl_xor_sync(0xffffffffu, r0, 1);
        r0 += __shfl_xor_sync(0xffffffffu, r0, 2);
        r1 += __shfl_xor_sync(0xffffffffu, r1, 1);
        r1 += __shfl_xor_sync(0xffffffffu, r1, 2);
        l0 = l0 * sc0 + r0;  m0 = mn0;
        l1 = l1 * sc1 + r1;  m1 = mn1;

        // rescale O
        #pragma unroll
        for (int nb = 0; nb < 12; nb++) {
            O[nb][0] *= sc0; O[nb][1] *= sc0;
            O[nb][2] *= sc1; O[nb][3] *= sc1;
        }

        // ---- P: C-frag -> A-frag (hi + lo residual)
        unsigned int ph[4][4], pl[4][4];
        #pragma unroll
        for (int kb = 0; kb < 4; kb++) {
            float f[8] = { S[2*kb][0], S[2*kb][1], S[2*kb][2], S[2*kb][3],
                           S[2*kb+1][0], S[2*kb+1][1], S[2*kb+1][2], S[2*kb+1][3] };
            #pragma unroll
            for (int rgp = 0; rgp < 4; rgp++) {
                unsigned int hw = pack_bf16x2(f[2*rgp], f[2*rgp+1]);
                ph[kb][rgp] = hw;
                pl[kb][rgp] = pack_bf16x2(f[2*rgp]   - bf16x2_lo(hw),
                                          f[2*rgp+1] - bf16x2_hi(hw));
            }
        }

        // ---- O += P V
        #pragma unroll
        for (int nb = 0; nb < 12; nb++) {
            int d = nb * 8 + (lane >> 2);
            #pragma unroll
            for (int kb = 0; kb < 4; kb++) {
                int w0 = kb * 8 + (lane & 3);
                unsigned int bhf[2] = { vh[d * 36 + w0], vh[d * 36 + w0 + 4] };
                unsigned int blf[2] = { vl[d * 36 + w0], vl[d * 36 + w0 + 4] };
                MMA_BF16(O[nb], ph[kb], bhf);
                MMA_BF16(O[nb], ph[kb], blf);
                MMA_BF16(O[nb], pl[kb], bhf);
            }
        }
    }

    // ---- epilogue: normalize, split to bf16 hi/lo, store
    float li0 = 1.0f / l0, li1 = 1.0f / l1;
    int tok0 = qrow0 + warp * 16 + (lane >> 2);
    int tok1 = tok0 + 8;
    #pragma unroll
    for (int nb = 0; nb < 12; nb++) {
        int wd = nb * 4 + (lane & 3);
        float c0 = O[nb][0] * li0, c1 = O[nb][1] * li0;
        float c2 = O[nb][2] * li1, c3 = O[nb][3] * li1;
        unsigned int hw0 = pack_bf16x2(c0, c1);
        unsigned int lw0 = pack_bf16x2(c0 - bf16x2_lo(hw0), c1 - bf16x2_hi(hw0));
        unsigned int hw1 = pack_bf16x2(c2, c3);
        unsigned int lw1 = pack_bf16x2(c2 - bf16x2_lo(hw1), c3 - bf16x2_hi(hw1));
        aohi[(size_t)tok0 * 768 + h48 + wd] = hw0;
        aolo[(size_t)tok0 * 768 + h48 + wd] = lw0;
        aohi[(size_t)tok1 * 768 + h48 + wd] = hw1;
        aolo[(size_t)tok1 * 768 + h48 + wd] = lw1;
    }
}

// ---------------------------------------------------------------------------
extern "C" void kernel_launch(void* const* d_in, const int* in_sizes, int n_in,
                              void* d_out, int out_size)
{
    const int*   xyz = (const int*)d_in[0];
    const float* h   = (const float*)d_in[1];
    const float* wq  = (const float*)d_in[2];
    const float* wk  = (const float*)d_in[3];
    const float* wv  = (const float*)d_in[4];
    const float* wo  = (const float*)d_in[5];
    float* out = (float*)d_out;

    float *pq, *pk, *pv;
    cudaGetSymbolAddress((void**)&pq,  g_q);
    cudaGetSymbolAddress((void**)&pk,  g_k);
    cudaGetSymbolAddress((void**)&pv,  g_v);

    __nv_bfloat16 *hh, *hl, *aoh, *aol;
    __nv_bfloat16 *wqh, *wql, *wkh, *wkl, *wvh, *wvl, *woh, *wol;
    cudaGetSymbolAddress((void**)&hh,  g_h_hi);  cudaGetSymbolAddress((void**)&hl,  g_h_lo);
    cudaGetSymbolAddress((void**)&aoh, g_ao_hi); cudaGetSymbolAddress((void**)&aol, g_ao_lo);
    cudaGetSymbolAddress((void**)&wqh, g_wq_hi); cudaGetSymbolAddress((void**)&wql, g_wq_lo);
    cudaGetSymbolAddress((void**)&wkh, g_wk_hi); cudaGetSymbolAddress((void**)&wkl, g_wk_lo);
    cudaGetSymbolAddress((void**)&wvh, g_wv_hi); cudaGetSymbolAddress((void**)&wvl, g_wv_lo);
    cudaGetSymbolAddress((void**)&woh, g_wo_hi); cudaGetSymbolAddress((void**)&wol, g_wo_lo);

    unsigned int *uqh, *uql, *ukh, *ukl, *uvh, *uvl;
    cudaGetSymbolAddress((void**)&uqh, g_qhi);  cudaGetSymbolAddress((void**)&uql, g_qlo);
    cudaGetSymbolAddress((void**)&ukh, g_khi);  cudaGetSymbolAddress((void**)&ukl, g_klo);
    cudaGetSymbolAddress((void**)&uvh, g_vthi); cudaGetSymbolAddress((void**)&uvl, g_vtlo);

    const int nH4 = NTOK * DIM / 4;
    const int nW4 = DIM * DIM / 4;
    split_bf16_kernel<<<(nH4 + 255)/256, 256>>>((const float4*)h,  (__nv_bfloat162*)hh,  (__nv_bfloat162*)hl,  nH4);
    split_bf16_kernel<<<(nW4 + 255)/256, 256>>>((const float4*)wq, (__nv_bfloat162*)wqh, (__nv_bfloat162*)wql, nW4);
    split_bf16_kernel<<<(nW4 + 255)/256, 256>>>((const float4*)wk, (__nv_bfloat162*)wkh, (__nv_bfloat162*)wkl, nW4);
    split_bf16_kernel<<<(nW4 + 255)/256, 256>>>((const float4*)wv, (__nv_bfloat162*)wvh, (__nv_bfloat162*)wvl, nW4);
    split_bf16_kernel<<<(nW4 + 255)/256, 256>>>((const float4*)wo, (__nv_bfloat162*)woh, (__nv_bfloat162*)wol, nW4);

    dim3 ggrid(DIM / 128, NTOK / 128);   // (12, 32)
    gemm_bf16x3_nt<<<ggrid, 256>>>(hh, hl, wqh, wql, pq, NTOK, DIM, DIM);
    gemm_bf16x3_nt<<<ggrid, 256>>>(hh, hl, wkh, wkl, pk, NTOK, DIM, DIM);
    gemm_bf16x3_nt<<<ggrid, 256>>>(hh, hl, wvh, wvl, pv, NTOK, DIM, DIM);

    int rope_threads = NTOK * NHD * 3 * 8;
    rope_split_kernel<<<rope_threads / 256, 256>>>(pq, pk, xyz, uqh, uql, ukh, ukl);

    dim3 vgrid(SS / 64, BB * NHD);
    vtrans_kernel<<<vgrid, 128>>>(pv, uvh, uvl);

    cudaFuncSetAttribute(attn_mma_kernel, cudaFuncAttributeMaxDynamicSharedMemorySize, ATT_SMEM_BYTES);
    dim3 agrid(SS / 64, BB * NHD);
    attn_mma_kernel<<<agrid, 128, ATT_SMEM_BYTES>>>(
        uqh, uql, ukh, ukl, uvh, uvl,
        (unsigned int*)aoh, (unsigned int*)aol);

    gemm_bf16x3_nt<<<ggrid, 256>>>(aoh, aol, woh, wol, out, NTOK, DIM, DIM);
}

// round 6
// speedup vs baseline: 3.5019x; 1.2810x over previous
#include <cuda_runtime.h>
#include <cuda_bf16.h>
#include <math_constants.h>
#include <cstdint>

// Problem constants
#define BB   2
#define SS   2048
#define DIM  1536
#define NHD  16
#define HD   96
#define NTOK (BB*SS)            // 4096
#define ATT_SCALE 0.10206207261596575f   // 1/sqrt(96)

// Scratch (device globals; allocation-free)
__device__ float g_q[NTOK * DIM];
__device__ float g_k[NTOK * DIM];
__device__ float g_v[NTOK * DIM];

__device__ __nv_bfloat16 g_h_hi[NTOK * DIM],  g_h_lo[NTOK * DIM];
__device__ __nv_bfloat16 g_ao_hi[NTOK * DIM], g_ao_lo[NTOK * DIM];
__device__ __nv_bfloat16 g_wq_hi[DIM * DIM],  g_wq_lo[DIM * DIM];
__device__ __nv_bfloat16 g_wk_hi[DIM * DIM],  g_wk_lo[DIM * DIM];
__device__ __nv_bfloat16 g_wv_hi[DIM * DIM],  g_wv_lo[DIM * DIM];
__device__ __nv_bfloat16 g_wo_hi[DIM * DIM],  g_wo_lo[DIM * DIM];

// Post-RoPE bf16 splits (q prescaled by ATT_SCALE), as uint32 bf16x2 words
__device__ unsigned int g_qhi[NTOK * DIM / 2], g_qlo[NTOK * DIM / 2];
__device__ unsigned int g_khi[NTOK * DIM / 2], g_klo[NTOK * DIM / 2];
// V transposed per (b,h): [32][96][2048] bf16 -> words [32][96][1024]
__device__ unsigned int g_vthi[32 * 96 * 1024], g_vtlo[32 * 96 * 1024];

// ---------------------------------------------------------------------------
// helpers
// ---------------------------------------------------------------------------
__device__ __forceinline__ unsigned int pack_bf16x2(float lo, float hi) {
    unsigned int r;
    asm("cvt.rn.bf16x2.f32 %0, %1, %2;" : "=r"(r) : "f"(hi), "f"(lo));
    return r;
}
__device__ __forceinline__ float bf16x2_lo(unsigned int w) {
    return __uint_as_float(w << 16);
}
__device__ __forceinline__ float bf16x2_hi(unsigned int w) {
    return __uint_as_float(w & 0xffff0000u);
}
__device__ __forceinline__ unsigned int smem_u32(const void* p) {
    unsigned int a;
    asm("{ .reg .u64 t; cvta.to.shared.u64 t, %1; cvt.u32.u64 %0, t; }"
        : "=r"(a) : "l"(p));
    return a;
}

#define MMA_BF16(d, a, b) \
  asm volatile("mma.sync.aligned.m16n8k16.row.col.f32.bf16.bf16.f32 " \
    "{%0,%1,%2,%3}, {%4,%5,%6,%7}, {%8,%9}, {%0,%1,%2,%3};" \
    : "+f"(d[0]), "+f"(d[1]), "+f"(d[2]), "+f"(d[3]) \
    : "r"(a[0]), "r"(a[1]), "r"(a[2]), "r"(a[3]), "r"(b[0]), "r"(b[1]))

#define LDSM4(r0, r1, r2, r3, addr) \
  asm volatile("ldmatrix.sync.aligned.m8n8.x4.shared.b16 {%0,%1,%2,%3}, [%4];" \
    : "=r"(r0), "=r"(r1), "=r"(r2), "=r"(r3) : "r"(addr))

#define CPA16(dst_s, src_g) \
  asm volatile("cp.async.ca.shared.global [%0], [%1], 16;" :: "r"(dst_s), "l"(src_g))
#define CPA16CG(dst_s, src_g) \
  asm volatile("cp.async.cg.shared.global [%0], [%1], 16;" :: "r"(dst_s), "l"(src_g))
#define CP_COMMIT() asm volatile("cp.async.commit_group;" ::: "memory")
#define CP_WAIT0()  asm volatile("cp.async.wait_group 0;" ::: "memory")

// ---------------------------------------------------------------------------
// fp32 -> (bf16 hi, bf16 lo) split. n multiple of 4.
// ---------------------------------------------------------------------------
__global__ void __launch_bounds__(256) split_bf16_kernel(
    const float4* __restrict__ x, __nv_bfloat162* __restrict__ hi,
    __nv_bfloat162* __restrict__ lo, int n4)
{
    int i = blockIdx.x * 256 + threadIdx.x;
    if (i >= n4) return;
    float4 v = x[i];
    __nv_bfloat16 h0 = __float2bfloat16(v.x);
    __nv_bfloat16 h1 = __float2bfloat16(v.y);
    __nv_bfloat16 h2 = __float2bfloat16(v.z);
    __nv_bfloat16 h3 = __float2bfloat16(v.w);
    __nv_bfloat16 l0 = __float2bfloat16(v.x - __bfloat162float(h0));
    __nv_bfloat16 l1 = __float2bfloat16(v.y - __bfloat162float(h1));
    __nv_bfloat16 l2 = __float2bfloat16(v.z - __bfloat162float(h2));
    __nv_bfloat16 l3 = __float2bfloat16(v.w - __bfloat162float(h3));
    __nv_bfloat162 a; a.x = h0; a.y = h1;
    __nv_bfloat162 b; b.x = h2; b.y = h3;
    __nv_bfloat162 c; c.x = l0; c.y = l1;
    __nv_bfloat162 d; d.x = l2; d.y = l3;
    hi[i*2]   = a; hi[i*2+1] = b;
    lo[i*2]   = c; lo[i*2+1] = d;
}

// ---------------------------------------------------------------------------
// ldmatrix tensor-core GEMM (bf16x3 split): C[m][n] = sum_k A[m][k]*W[n][k]
// CTA 128x128 tile, BK=64 (SW128 128B rows), 256 threads (8 warps, 2x4),
// warp tile 64x32. cp.async double-buffered; ldmatrix.x4 consumers.
// grid.z selects one of 3 (W, C) pairs (QKV fusion).
// ---------------------------------------------------------------------------
#define GL_STAGE 65536     // 4 tiles (Ahi,Alo,Bhi,Blo) x 128 rows x 128B
#define GL_SMEM  (2 * GL_STAGE)
#define GL_NC    (DIM / 64)   // 24

struct GemmPtrs {
    const __nv_bfloat16 *bh0, *bl0, *bh1, *bl1, *bh2, *bl2;
    float *c0, *c1, *c2;
};

__device__ __forceinline__ void gl_prefetch(
    unsigned int stage_base,
    const __nv_bfloat16* __restrict__ a_h, const __nv_bfloat16* __restrict__ a_l,
    const __nv_bfloat16* __restrict__ b_h, const __nv_bfloat16* __restrict__ b_l,
    int tid, int koff)
{
    #pragma unroll
    for (int t = 0; t < 4; t++) {
        const __nv_bfloat16* s = (t == 0) ? a_h : (t == 1) ? a_l : (t == 2) ? b_h : b_l;
        #pragma unroll
        for (int i = 0; i < 4; i++) {
            int w = tid + 256 * i;          // 0..1023
            int r = w >> 3, cc = w & 7;     // row, 16B chunk
            unsigned int off = r * 128 + cc * 16;
            unsigned int dst = stage_base + t * 16384 + (off ^ ((off >> 3) & 0x70));
            CPA16CG(dst, s + (size_t)r * DIM + koff + cc * 8);
        }
    }
    CP_COMMIT();
}

__global__ void __launch_bounds__(256, 1) gemm_ldsm_nt(
    const __nv_bfloat16* __restrict__ Ahi, const __nv_bfloat16* __restrict__ Alo,
    GemmPtrs P)
{
    extern __shared__ char smraw[];
    const unsigned int sbase = smem_u32(smraw);
    const int tid  = threadIdx.x;
    const int lane = tid & 31;
    const int warp = tid >> 5;
    const int warp_m = warp >> 2;    // 0..1
    const int warp_n = warp & 3;     // 0..3
    const int row0 = blockIdx.y * 128;
    const int col0 = blockIdx.x * 128;
    const int z = blockIdx.z;

    const __nv_bfloat16* Whi = (z == 0) ? P.bh0 : (z == 1) ? P.bh1 : P.bh2;
    const __nv_bfloat16* Wlo = (z == 0) ? P.bl0 : (z == 1) ? P.bl1 : P.bl2;
    float* C = (z == 0) ? P.c0 : (z == 1) ? P.c1 : P.c2;

    const __nv_bfloat16* a_h = Ahi + (size_t)row0 * DIM;
    const __nv_bfloat16* a_l = Alo + (size_t)row0 * DIM;
    const __nv_bfloat16* b_h = Whi + (size_t)col0 * DIM;
    const __nv_bfloat16* b_l = Wlo + (size_t)col0 * DIM;

    // ldmatrix lane address components
    const int g = lane >> 3, j = lane & 7;
    const unsigned int rA = warp_m * 64 + (g & 1) * 8 + j;   // + mbl*16
    const unsigned int cA = (g >> 1) * 16;                   // + kc*32
    const unsigned int rB = warp_n * 32 + (g >> 1) * 8 + j;  // + nb2*16
    const unsigned int cB = (g & 1) * 16;

    float acc[4][4][4] = {};    // [mbl][nbl][reg]

    gl_prefetch(sbase, a_h, a_l, b_h, b_l, tid, 0);

    for (int c = 0; c < GL_NC; c++) {
        CP_WAIT0();
        __syncthreads();
        if (c + 1 < GL_NC)
            gl_prefetch(sbase + ((c + 1) & 1) * GL_STAGE, a_h, a_l, b_h, b_l,
                        tid, (c + 1) * 64);

        const unsigned int stb = sbase + (c & 1) * GL_STAGE;

        #pragma unroll
        for (int kc = 0; kc < 4; kc++) {
            unsigned int ah[4][4], al[4][4];
            #pragma unroll
            for (int mbl = 0; mbl < 4; mbl++) {
                unsigned int off = (rA + mbl * 16) * 128 + cA + kc * 32;
                unsigned int sw = off ^ ((off >> 3) & 0x70);
                LDSM4(ah[mbl][0], ah[mbl][1], ah[mbl][2], ah[mbl][3], stb + sw);
                LDSM4(al[mbl][0], al[mbl][1], al[mbl][2], al[mbl][3], stb + 16384 + sw);
            }
            unsigned int bh[4][2], bl[4][2];
            #pragma unroll
            for (int nb2 = 0; nb2 < 2; nb2++) {
                unsigned int off = (rB + nb2 * 16) * 128 + cB + kc * 32;
                unsigned int sw = off ^ ((off >> 3) & 0x70);
                unsigned int r0, r1, r2, r3;
                LDSM4(r0, r1, r2, r3, stb + 32768 + sw);
                bh[2*nb2][0] = r0; bh[2*nb2][1] = r1;
                bh[2*nb2+1][0] = r2; bh[2*nb2+1][1] = r3;
                LDSM4(r0, r1, r2, r3, stb + 49152 + sw);
                bl[2*nb2][0] = r0; bl[2*nb2][1] = r1;
                bl[2*nb2+1][0] = r2; bl[2*nb2+1][1] = r3;
            }
            #pragma unroll
            for (int mbl = 0; mbl < 4; mbl++)
                #pragma unroll
                for (int nbl = 0; nbl < 4; nbl++) {
                    MMA_BF16(acc[mbl][nbl], ah[mbl], bh[nbl]);   // hi*hi
                    MMA_BF16(acc[mbl][nbl], ah[mbl], bl[nbl]);   // hi*lo
                    MMA_BF16(acc[mbl][nbl], al[mbl], bh[nbl]);   // lo*hi
                }
        }
    }

    #pragma unroll
    for (int mbl = 0; mbl < 4; mbl++) {
        int mrow = row0 + warp_m * 64 + mbl * 16 + (lane >> 2);
        #pragma unroll
        for (int nbl = 0; nbl < 4; nbl++) {
            int ncol = col0 + warp_n * 32 + nbl * 8 + (lane & 3) * 2;
            float2 v0 = make_float2(acc[mbl][nbl][0], acc[mbl][nbl][1]);
            float2 v1 = make_float2(acc[mbl][nbl][2], acc[mbl][nbl][3]);
            *(float2*)&C[(size_t)mrow * DIM + ncol]       = v0;
            *(float2*)&C[(size_t)(mrow + 8) * DIM + ncol] = v1;
        }
    }
}

// ---------------------------------------------------------------------------
// RoPE + bf16 split: q,k fp32 -> qhi/qlo/khi/klo bf16x2 words.
// ---------------------------------------------------------------------------
__global__ void __launch_bounds__(256) rope_split_kernel(
    const float* __restrict__ q, const float* __restrict__ k,
    const int* __restrict__ xyz,
    unsigned int* __restrict__ qhi, unsigned int* __restrict__ qlo,
    unsigned int* __restrict__ khi, unsigned int* __restrict__ klo)
{
    int idx = blockIdx.x * 256 + threadIdx.x;   // NTOK*16*3*8
    int j2 = idx & 7;
    int p  = (idx >> 3) % 3;
    int th = idx / 24;
    int h  = th & 15;
    int t  = th >> 4;
    if (t >= NTOK) return;

    float pos = (float)xyz[t * 3 + p];
    const float c = 0.83048202372184058696f;   // log2(10000)/16
    int j0 = 2 * j2;
    float s0, c0, s1, c1;
    sincosf(pos * exp2f(-(float)j0 * c), &s0, &c0);
    sincosf(pos * exp2f(-(float)(j0 + 1) * c), &s1, &c1);

    int base = t * DIM + h * HD + p * 32 + j0;
    int wbase = t * (DIM/2) + h * (HD/2) + p * 16 + j2;

    {
        float2 a = *(const float2*)&q[base];
        float2 b = *(const float2*)&q[base + 16];
        float o1x = (a.x * c0 - b.x * s0) * ATT_SCALE;
        float o1y = (a.y * c1 - b.y * s1) * ATT_SCALE;
        float o2x = (b.x * c0 + a.x * s0) * ATT_SCALE;
        float o2y = (b.y * c1 + a.y * s1) * ATT_SCALE;
        unsigned int h1 = pack_bf16x2(o1x, o1y);
        unsigned int h2 = pack_bf16x2(o2x, o2y);
        unsigned int l1 = pack_bf16x2(o1x - bf16x2_lo(h1), o1y - bf16x2_hi(h1));
        unsigned int l2 = pack_bf16x2(o2x - bf16x2_lo(h2), o2y - bf16x2_hi(h2));
        qhi[wbase] = h1; qhi[wbase + 8] = h2;
        qlo[wbase] = l1; qlo[wbase + 8] = l2;
    }
    {
        float2 a = *(const float2*)&k[base];
        float2 b = *(const float2*)&k[base + 16];
        float o1x = a.x * c0 - b.x * s0;
        float o1y = a.y * c1 - b.y * s1;
        float o2x = b.x * c0 + a.x * s0;
        float o2y = b.y * c1 + a.y * s1;
        unsigned int h1 = pack_bf16x2(o1x, o1y);
        unsigned int h2 = pack_bf16x2(o2x, o2y);
        unsigned int l1 = pack_bf16x2(o1x - bf16x2_lo(h1), o1y - bf16x2_hi(h1));
        unsigned int l2 = pack_bf16x2(o2x - bf16x2_lo(h2), o2y - bf16x2_hi(h2));
        khi[wbase] = h1; khi[wbase + 8] = h2;
        klo[wbase] = l1; klo[wbase + 8] = l2;
    }
}

// ---------------------------------------------------------------------------
// V transpose + split
// ---------------------------------------------------------------------------
__global__ void __launch_bounds__(128) vtrans_kernel(
    const float* __restrict__ v,
    unsigned int* __restrict__ vthi, unsigned int* __restrict__ vtlo)
{
    __shared__ float sm[96 * 65];
    const int tid = threadIdx.x;
    const int bh = blockIdx.y;
    const int b = bh >> 4, h = bh & 15;
    const int s0 = blockIdx.x * 64;

    {
        int s = tid >> 1, half = tid & 1;
        const float* src = v + (size_t)(b * SS + s0 + s) * DIM + h * HD + half * 48;
        #pragma unroll
        for (int i = 0; i < 12; i++) {
            float4 x = *(const float4*)(src + i * 4);
            int d = half * 48 + i * 4;
            sm[(d + 0) * 65 + s] = x.x;
            sm[(d + 1) * 65 + s] = x.y;
            sm[(d + 2) * 65 + s] = x.z;
            sm[(d + 3) * 65 + s] = x.w;
        }
    }
    __syncthreads();

    #pragma unroll
    for (int i = 0; i < 24; i++) {
        int w = tid + 128 * i;
        int d = w >> 5, j = w & 31;
        float f0 = sm[d * 65 + 2 * j];
        float f1 = sm[d * 65 + 2 * j + 1];
        unsigned int hi = pack_bf16x2(f0, f1);
        unsigned int lo = pack_bf16x2(f0 - bf16x2_lo(hi), f1 - bf16x2_hi(hi));
        size_t dst = (size_t)(bh * 96 + d) * 1024 + (s0 >> 1) + j;
        vthi[dst] = hi;
        vtlo[dst] = lo;
    }
}

// ---------------------------------------------------------------------------
// MMA flash attention (unchanged from R4, passing)
// ---------------------------------------------------------------------------
#define AKHI 0
#define AKLO 3328
#define AVHI 6656
#define AVLO 10112
#define ABUF 13568
#define ATT_SMEM_BYTES (2 * ABUF * 4)

__global__ void __launch_bounds__(128, 2) attn_mma_kernel(
    const unsigned int* __restrict__ qhi, const unsigned int* __restrict__ qlo,
    const unsigned int* __restrict__ khi, const unsigned int* __restrict__ klo,
    const unsigned int* __restrict__ vthi, const unsigned int* __restrict__ vtlo,
    unsigned int* __restrict__ aohi, unsigned int* __restrict__ aolo)
{
    extern __shared__ unsigned int smw[];
    unsigned int sbase = smem_u32(smw);

    const int tid  = threadIdx.x;
    const int lane = tid & 31;
    const int warp = tid >> 5;
    const int qt = blockIdx.x;
    const int bh = blockIdx.y;
    const int b = bh >> 4, h = bh & 15;
    const int h48 = h * 48;
    const int qrow0 = b * SS + qt * 64;

    unsigned int qh[6][4], ql[6][4];
    {
        const unsigned int* qhg = qhi + (size_t)qrow0 * 768 + h48;
        const unsigned int* qlg = qlo + (size_t)qrow0 * 768 + h48;
        int r0 = warp * 16 + (lane >> 2);
        #pragma unroll
        for (int kb = 0; kb < 6; kb++) {
            int w0 = kb * 8 + (lane & 3);
            qh[kb][0] = qhg[(size_t)r0 * 768 + w0];
            qh[kb][1] = qhg[(size_t)(r0 + 8) * 768 + w0];
            qh[kb][2] = qhg[(size_t)r0 * 768 + w0 + 4];
            qh[kb][3] = qhg[(size_t)(r0 + 8) * 768 + w0 + 4];
            ql[kb][0] = qlg[(size_t)r0 * 768 + w0];
            ql[kb][1] = qlg[(size_t)(r0 + 8) * 768 + w0];
            ql[kb][2] = qlg[(size_t)r0 * 768 + w0 + 4];
            ql[kb][3] = qlg[(size_t)(r0 + 8) * 768 + w0 + 4];
        }
    }

    float O[12][4];
    #pragma unroll
    for (int nb = 0; nb < 12; nb++)
        #pragma unroll
        for (int i = 0; i < 4; i++) O[nb][i] = 0.0f;
    float m0 = -CUDART_INF_F, m1 = -CUDART_INF_F, l0 = 0.0f, l1 = 0.0f;

    const unsigned int* ksrc[2] = { khi, klo };
    const unsigned int* vsrc[2] = { vthi, vtlo };

#define PREFETCH(bi, ktv)                                                      \
    {                                                                          \
        int ktok = b * SS + (ktv) * 64;                                        \
        _Pragma("unroll")                                                      \
        for (int hl = 0; hl < 2; hl++) {                                       \
            const unsigned int* sk = ksrc[hl];                                 \
            _Pragma("unroll")                                                  \
            for (int i = 0; i < 6; i++) {                                      \
                int cc = tid + 128 * i;                                        \
                int key = cc / 12, j = cc - key * 12;                          \
                unsigned int dw = ((bi) * ABUF + hl * AKLO + key * 52 + j * 4);\
                CPA16(sbase + dw * 4,                                          \
                      sk + (size_t)(ktok + key) * 768 + h48 + j * 4);          \
            }                                                                  \
            const unsigned int* sv = vsrc[hl];                                 \
            _Pragma("unroll")                                                  \
            for (int i = 0; i < 6; i++) {                                      \
                int cc = tid + 128 * i;                                        \
                int d = cc >> 3, j = cc & 7;                                   \
                unsigned int dw = ((bi) * ABUF + AVHI + hl * (AVLO - AVHI)     \
                                   + d * 36 + j * 4);                          \
                CPA16(sbase + dw * 4,                                          \
                      sv + (size_t)(bh * 96 + d) * 1024 + (ktv) * 32 + j * 4); \
            }                                                                  \
        }                                                                      \
        CP_COMMIT();                                                           \
    }

    PREFETCH(0, 0);

    for (int kt = 0; kt < SS / 64; kt++) {
        CP_WAIT0();
        __syncthreads();
        if (kt + 1 < SS / 64) PREFETCH((kt + 1) & 1, kt + 1);

        const unsigned int* kh = smw + (kt & 1) * ABUF + AKHI;
        const unsigned int* kl = smw + (kt & 1) * ABUF + AKLO;
        const unsigned int* vh = smw + (kt & 1) * ABUF + AVHI;
        const unsigned int* vl = smw + (kt & 1) * ABUF + AVLO;

        float S[8][4];
        #pragma unroll
        for (int nb = 0; nb < 8; nb++) {
            #pragma unroll
            for (int i = 0; i < 4; i++) S[nb][i] = 0.0f;
            int key = nb * 8 + (lane >> 2);
            #pragma unroll
            for (int kb = 0; kb < 6; kb++) {
                int w0 = kb * 8 + (lane & 3);
                unsigned int bhf[2] = { kh[key * 52 + w0], kh[key * 52 + w0 + 4] };
                unsigned int blf[2] = { kl[key * 52 + w0], kl[key * 52 + w0 + 4] };
                MMA_BF16(S[nb], qh[kb], bhf);
                MMA_BF16(S[nb], qh[kb], blf);
                MMA_BF16(S[nb], ql[kb], bhf);
            }
        }

        float ml0 = -CUDART_INF_F, ml1 = -CUDART_INF_F;
        #pragma unroll
        for (int nb = 0; nb < 8; nb++) {
            ml0 = fmaxf(ml0, fmaxf(S[nb][0], S[nb][1]));
            ml1 = fmaxf(ml1, fmaxf(S[nb][2], S[nb][3]));
        }
        ml0 = fmaxf(ml0, __shfl_xor_sync(0xffffffffu, ml0, 1));
        ml0 = fmaxf(ml0, __shfl_xor_sync(0xffffffffu, ml0, 2));
        ml1 = fmaxf(ml1, __shfl_xor_sync(0xffffffffu, ml1, 1));
        ml1 = fmaxf(ml1, __shfl_xor_sync(0xffffffffu, ml1, 2));
        float mn0 = fmaxf(m0, ml0), mn1 = fmaxf(m1, ml1);
        float sc0 = __expf(m0 - mn0), sc1 = __expf(m1 - mn1);
        float r0 = 0.0f, r1 = 0.0f;
        #pragma unroll
        for (int nb = 0; nb < 8; nb++) {
            S[nb][0] = __expf(S[nb][0] - mn0);
            S[nb][1] = __expf(S[nb][1] - mn0);
            S[nb][2] = __expf(S[nb][2] - mn1);
            S[nb][3] = __expf(S[nb][3] - mn1);
            r0 += S[nb][0] + S[nb][1];
            r1 += S[nb][2] + S[nb][3];
        }
        r0 += __shfl_xor_sync(0xffffffffu, r0, 1);
        r0 += __shfl_xor_sync(0xffffffffu, r0, 2);
        r1 += __shfl_xor_sync(0xffffffffu, r1, 1);
        r1 += __shfl_xor_sync(0xffffffffu, r1, 2);
        l0 = l0 * sc0 + r0;  m0 = mn0;
        l1 = l1 * sc1 + r1;  m1 = mn1;

        #pragma unroll
        for (int nb = 0; nb < 12; nb++) {
            O[nb][0] *= sc0; O[nb][1] *= sc0;
            O[nb][2] *= sc1; O[nb][3] *= sc1;
        }

        unsigned int ph[4][4], pl[4][4];
        #pragma unroll
        for (int kb = 0; kb < 4; kb++) {
            float f[8] = { S[2*kb][0], S[2*kb][1], S[2*kb][2], S[2*kb][3],
                           S[2*kb+1][0], S[2*kb+1][1], S[2*kb+1][2], S[2*kb+1][3] };
            #pragma unroll
            for (int rgp = 0; rgp < 4; rgp++) {
                unsigned int hw = pack_bf16x2(f[2*rgp], f[2*rgp+1]);
                ph[kb][rgp] = hw;
                pl[kb][rgp] = pack_bf16x2(f[2*rgp]   - bf16x2_lo(hw),
                                          f[2*rgp+1] - bf16x2_hi(hw));
            }
        }

        #pragma unroll
        for (int nb = 0; nb < 12; nb++) {
            int d = nb * 8 + (lane >> 2);
            #pragma unroll
            for (int kb = 0; kb < 4; kb++) {
                int w0 = kb * 8 + (lane & 3);
                unsigned int bhf[2] = { vh[d * 36 + w0], vh[d * 36 + w0 + 4] };
                unsigned int blf[2] = { vl[d * 36 + w0], vl[d * 36 + w0 + 4] };
                MMA_BF16(O[nb], ph[kb], bhf);
                MMA_BF16(O[nb], ph[kb], blf);
                MMA_BF16(O[nb], pl[kb], bhf);
            }
        }
    }

    float li0 = 1.0f / l0, li1 = 1.0f / l1;
    int tok0 = qrow0 + warp * 16 + (lane >> 2);
    int tok1 = tok0 + 8;
    #pragma unroll
    for (int nb = 0; nb < 12; nb++) {
        int wd = nb * 4 + (lane & 3);
        float c0 = O[nb][0] * li0, c1 = O[nb][1] * li0;
        float c2 = O[nb][2] * li1, c3 = O[nb][3] * li1;
        unsigned int hw0 = pack_bf16x2(c0, c1);
        unsigned int lw0 = pack_bf16x2(c0 - bf16x2_lo(hw0), c1 - bf16x2_hi(hw0));
        unsigned int hw1 = pack_bf16x2(c2, c3);
        unsigned int lw1 = pack_bf16x2(c2 - bf16x2_lo(hw1), c3 - bf16x2_hi(hw1));
        aohi[(size_t)tok0 * 768 + h48 + wd] = hw0;
        aolo[(size_t)tok0 * 768 + h48 + wd] = lw0;
        aohi[(size_t)tok1 * 768 + h48 + wd] = hw1;
        aolo[(size_t)tok1 * 768 + h48 + wd] = lw1;
    }
}

// ---------------------------------------------------------------------------
extern "C" void kernel_launch(void* const* d_in, const int* in_sizes, int n_in,
                              void* d_out, int out_size)
{
    const int*   xyz = (const int*)d_in[0];
    const float* h   = (const float*)d_in[1];
    const float* wq  = (const float*)d_in[2];
    const float* wk  = (const float*)d_in[3];
    const float* wv  = (const float*)d_in[4];
    const float* wo  = (const float*)d_in[5];
    float* out = (float*)d_out;

    float *pq, *pk, *pv;
    cudaGetSymbolAddress((void**)&pq,  g_q);
    cudaGetSymbolAddress((void**)&pk,  g_k);
    cudaGetSymbolAddress((void**)&pv,  g_v);

    __nv_bfloat16 *hh, *hl, *aoh, *aol;
    __nv_bfloat16 *wqh, *wql, *wkh, *wkl, *wvh, *wvl, *woh, *wol;
    cudaGetSymbolAddress((void**)&hh,  g_h_hi);  cudaGetSymbolAddress((void**)&hl,  g_h_lo);
    cudaGetSymbolAddress((void**)&aoh, g_ao_hi); cudaGetSymbolAddress((void**)&aol, g_ao_lo);
    cudaGetSymbolAddress((void**)&wqh, g_wq_hi); cudaGetSymbolAddress((void**)&wql, g_wq_lo);
    cudaGetSymbolAddress((void**)&wkh, g_wk_hi); cudaGetSymbolAddress((void**)&wkl, g_wk_lo);
    cudaGetSymbolAddress((void**)&wvh, g_wv_hi); cudaGetSymbolAddress((void**)&wvl, g_wv_lo);
    cudaGetSymbolAddress((void**)&woh, g_wo_hi); cudaGetSymbolAddress((void**)&wol, g_wo_lo);

    unsigned int *uqh, *uql, *ukh, *ukl, *uvh, *uvl;
    cudaGetSymbolAddress((void**)&uqh, g_qhi);  cudaGetSymbolAddress((void**)&uql, g_qlo);
    cudaGetSymbolAddress((void**)&ukh, g_khi);  cudaGetSymbolAddress((void**)&ukl, g_klo);
    cudaGetSymbolAddress((void**)&uvh, g_vthi); cudaGetSymbolAddress((void**)&uvl, g_vtlo);

    const int nH4 = NTOK * DIM / 4;
    const int nW4 = DIM * DIM / 4;
    split_bf16_kernel<<<(nH4 + 255)/256, 256>>>((const float4*)h,  (__nv_bfloat162*)hh,  (__nv_bfloat162*)hl,  nH4);
    split_bf16_kernel<<<(nW4 + 255)/256, 256>>>((const float4*)wq, (__nv_bfloat162*)wqh, (__nv_bfloat162*)wql, nW4);
    split_bf16_kernel<<<(nW4 + 255)/256, 256>>>((const float4*)wk, (__nv_bfloat162*)wkh, (__nv_bfloat162*)wkl, nW4);
    split_bf16_kernel<<<(nW4 + 255)/256, 256>>>((const float4*)wv, (__nv_bfloat162*)wvh, (__nv_bfloat162*)wvl, nW4);
    split_bf16_kernel<<<(nW4 + 255)/256, 256>>>((const float4*)wo, (__nv_bfloat162*)woh, (__nv_bfloat162*)wol, nW4);

    cudaFuncSetAttribute(gemm_ldsm_nt, cudaFuncAttributeMaxDynamicSharedMemorySize, GL_SMEM);

    // fused QKV projections
    GemmPtrs Pqkv;
    Pqkv.bh0 = wqh; Pqkv.bl0 = wql;
    Pqkv.bh1 = wkh; Pqkv.bl1 = wkl;
    Pqkv.bh2 = wvh; Pqkv.bl2 = wvl;
    Pqkv.c0 = pq; Pqkv.c1 = pk; Pqkv.c2 = pv;
    dim3 gq(DIM / 128, NTOK / 128, 3);   // (12, 32, 3)
    gemm_ldsm_nt<<<gq, 256, GL_SMEM>>>(hh, hl, Pqkv);

    int rope_threads = NTOK * NHD * 3 * 8;
    rope_split_kernel<<<rope_threads / 256, 256>>>(pq, pk, xyz, uqh, uql, ukh, ukl);

    dim3 vgrid(SS / 64, BB * NHD);
    vtrans_kernel<<<vgrid, 128>>>(pv, uvh, uvl);

    cudaFuncSetAttribute(attn_mma_kernel, cudaFuncAttributeMaxDynamicSharedMemorySize, ATT_SMEM_BYTES);
    dim3 agrid(SS / 64, BB * NHD);
    attn_mma_kernel<<<agrid, 128, ATT_SMEM_BYTES>>>(
        uqh, uql, ukh, ukl, uvh, uvl,
        (unsigned int*)aoh, (unsigned int*)aol);

    // O projection
    GemmPtrs Po;
    Po.bh0 = woh; Po.bl0 = wol;
    Po.bh1 = woh; Po.bl1 = wol;
    Po.bh2 = woh; Po.bl2 = wol;
    Po.c0 = out; Po.c1 = out; Po.c2 = out;
    dim3 go(DIM / 128, NTOK / 128, 1);
    gemm_ldsm_nt<<<go, 256, GL_SMEM>>>(aoh, aol, Po);
}

// round 8
// speedup vs baseline: 5.5916x; 1.5967x over previous
#include <cuda_runtime.h>
#include <cuda_fp16.h>
#include <math_constants.h>
#include <cstdint>

// Problem constants
#define BB   2
#define SS   2048
#define DIM  1536
#define NHD  16
#define HD   96
#define NTOK (BB*SS)            // 4096
#define ATT_SCALE 0.10206207261596575f   // 1/sqrt(96)

// Scratch (device globals; allocation-free)
__device__ float g_q[NTOK * DIM];
__device__ float g_k[NTOK * DIM];
__device__ float g_v[NTOK * DIM];

__device__ __half g_h_hi[NTOK * DIM],  g_h_lo[NTOK * DIM];
__device__ __half g_ao_hi[NTOK * DIM], g_ao_lo[NTOK * DIM];
__device__ __half g_wq_hi[DIM * DIM];
__device__ __half g_wk_hi[DIM * DIM];
__device__ __half g_wv_hi[DIM * DIM];
__device__ __half g_wo_hi[DIM * DIM];

// Post-RoPE fp16 (q split + prescaled by ATT_SCALE; k rounded), f16x2 words
__device__ unsigned int g_qhi[NTOK * DIM / 2], g_qlo[NTOK * DIM / 2];
__device__ unsigned int g_khi[NTOK * DIM / 2];
// V transposed per (b,h): [32][96][2048] fp16 -> words [32][96][1024]
__device__ unsigned int g_vthi[32 * 96 * 1024];

// ---------------------------------------------------------------------------
// helpers
// ---------------------------------------------------------------------------
__device__ __forceinline__ unsigned int pack_f16x2(float lo, float hi) {
    unsigned int r;
    asm("cvt.rn.f16x2.f32 %0, %1, %2;" : "=r"(r) : "f"(hi), "f"(lo));
    return r;
}
__device__ __forceinline__ float f16x2_lo(unsigned int w) {
    float f;
    asm("{ .reg .b16 l, h; mov.b32 {l, h}, %1; cvt.f32.f16 %0, l; }" : "=f"(f) : "r"(w));
    return f;
}
__device__ __forceinline__ float f16x2_hi(unsigned int w) {
    float f;
    asm("{ .reg .b16 l, h; mov.b32 {l, h}, %1; cvt.f32.f16 %0, h; }" : "=f"(f) : "r"(w));
    return f;
}
__device__ __forceinline__ unsigned int smem_u32(const void* p) {
    unsigned int a;
    asm("{ .reg .u64 t; cvta.to.shared.u64 t, %1; cvt.u32.u64 %0, t; }"
        : "=r"(a) : "l"(p));
    return a;
}

#define MMA_F16(d, a, b) \
  asm volatile("mma.sync.aligned.m16n8k16.row.col.f32.f16.f16.f32 " \
    "{%0,%1,%2,%3}, {%4,%5,%6,%7}, {%8,%9}, {%0,%1,%2,%3};" \
    : "+f"(d[0]), "+f"(d[1]), "+f"(d[2]), "+f"(d[3]) \
    : "r"(a[0]), "r"(a[1]), "r"(a[2]), "r"(a[3]), "r"(b[0]), "r"(b[1]))

#define LDSM4(r0, r1, r2, r3, addr) \
  asm volatile("ldmatrix.sync.aligned.m8n8.x4.shared.b16 {%0,%1,%2,%3}, [%4];" \
    : "=r"(r0), "=r"(r1), "=r"(r2), "=r"(r3) : "r"(addr))

#define CPA16(dst_s, src_g) \
  asm volatile("cp.async.ca.shared.global [%0], [%1], 16;" :: "r"(dst_s), "l"(src_g))
#define CPA16CG(dst_s, src_g) \
  asm volatile("cp.async.cg.shared.global [%0], [%1], 16;" :: "r"(dst_s), "l"(src_g))
#define CP_COMMIT() asm volatile("cp.async.commit_group;" ::: "memory")
#define CP_WAIT0()  asm volatile("cp.async.wait_group 0;" ::: "memory")

// ---------------------------------------------------------------------------
// fp32 -> (fp16 hi, fp16 lo) split. n multiple of 4.
// ---------------------------------------------------------------------------
__global__ void __launch_bounds__(256) split_fp16_kernel(
    const float4* __restrict__ x, unsigned int* __restrict__ hi,
    unsigned int* __restrict__ lo, int n4)
{
    int i = blockIdx.x * 256 + threadIdx.x;
    if (i >= n4) return;
    float4 v = x[i];
    unsigned int h0 = pack_f16x2(v.x, v.y);
    unsigned int h1 = pack_f16x2(v.z, v.w);
    unsigned int l0 = pack_f16x2(v.x - f16x2_lo(h0), v.y - f16x2_hi(h0));
    unsigned int l1 = pack_f16x2(v.z - f16x2_lo(h1), v.w - f16x2_hi(h1));
    hi[i*2] = h0; hi[i*2+1] = h1;
    lo[i*2] = l0; lo[i*2+1] = l1;
}

// fp32 -> fp16 round (weights: B operand only needs hi)
__global__ void __launch_bounds__(256) round_fp16_kernel(
    const float4* __restrict__ x, unsigned int* __restrict__ hi, int n4)
{
    int i = blockIdx.x * 256 + threadIdx.x;
    if (i >= n4) return;
    float4 v = x[i];
    hi[i*2]   = pack_f16x2(v.x, v.y);
    hi[i*2+1] = pack_f16x2(v.z, v.w);
}

// ---------------------------------------------------------------------------
// ldmatrix tensor-core GEMM (fp16 A-split x fp16 B): C[m][n]=sum_k A[m][k]W[n][k]
// CTA 128x128, BK=64 (SW128 128B rows), 256 threads (8 warps 2x4), warp 64x32.
// Tiles per stage: Ahi, Alo, Bhi (48KB). Double buffered. grid.z = QKV fusion.
// ---------------------------------------------------------------------------
#define GL_STAGE 49152     // 3 tiles x 128 rows x 128B
#define GL_SMEM  (2 * GL_STAGE)
#define GL_NC    (DIM / 64)   // 24

struct GemmPtrs {
    const __half *b0, *b1, *b2;
    float *c0, *c1, *c2;
};

__device__ __forceinline__ void gl_prefetch(
    unsigned int stage_base,
    const __half* __restrict__ a_h, const __half* __restrict__ a_l,
    const __half* __restrict__ b_h,
    int tid, int koff)
{
    #pragma unroll
    for (int t = 0; t < 3; t++) {
        const __half* s = (t == 0) ? a_h : (t == 1) ? a_l : b_h;
        #pragma unroll
        for (int i = 0; i < 4; i++) {
            int w = tid + 256 * i;          // 0..1023
            int r = w >> 3, cc = w & 7;     // row, 16B chunk
            unsigned int off = r * 128 + cc * 16;
            unsigned int dst = stage_base + t * 16384 + (off ^ ((off >> 3) & 0x70));
            CPA16CG(dst, s + (size_t)r * DIM + koff + cc * 8);
        }
    }
    CP_COMMIT();
}

__global__ void __launch_bounds__(256, 2) gemm_ldsm_nt(
    const __half* __restrict__ Ahi, const __half* __restrict__ Alo,
    GemmPtrs P)
{
    extern __shared__ char smraw[];
    const unsigned int sbase = smem_u32(smraw);
    const int tid  = threadIdx.x;
    const int lane = tid & 31;
    const int warp = tid >> 5;
    const int warp_m = warp >> 2;    // 0..1
    const int warp_n = warp & 3;     // 0..3
    const int row0 = blockIdx.y * 128;
    const int col0 = blockIdx.x * 128;
    const int z = blockIdx.z;

    const __half* Whi = (z == 0) ? P.b0 : (z == 1) ? P.b1 : P.b2;
    float* C = (z == 0) ? P.c0 : (z == 1) ? P.c1 : P.c2;

    const __half* a_h = Ahi + (size_t)row0 * DIM;
    const __half* a_l = Alo + (size_t)row0 * DIM;
    const __half* b_h = Whi + (size_t)col0 * DIM;

    // ldmatrix lane address components
    const int g = lane >> 3, j = lane & 7;
    const unsigned int rA = warp_m * 64 + (g & 1) * 8 + j;   // + mbl*16
    const unsigned int cA = (g >> 1) * 16;                   // + kc*32
    const unsigned int rB = warp_n * 32 + (g >> 1) * 8 + j;  // + nb2*16
    const unsigned int cB = (g & 1) * 16;

    float acc[4][4][4] = {};    // [mbl][nbl][reg]

    gl_prefetch(sbase, a_h, a_l, b_h, tid, 0);

    for (int c = 0; c < GL_NC; c++) {
        CP_WAIT0();
        __syncthreads();
        if (c + 1 < GL_NC)
            gl_prefetch(sbase + ((c + 1) & 1) * GL_STAGE, a_h, a_l, b_h,
                        tid, (c + 1) * 64);

        const unsigned int stb = sbase + (c & 1) * GL_STAGE;

        #pragma unroll
        for (int kc = 0; kc < 4; kc++) {
            unsigned int ah[4][4], al[4][4];
            #pragma unroll
            for (int mbl = 0; mbl < 4; mbl++) {
                unsigned int off = (rA + mbl * 16) * 128 + cA + kc * 32;
                unsigned int sw = off ^ ((off >> 3) & 0x70);
                LDSM4(ah[mbl][0], ah[mbl][1], ah[mbl][2], ah[mbl][3], stb + sw);
                LDSM4(al[mbl][0], al[mbl][1], al[mbl][2], al[mbl][3], stb + 16384 + sw);
            }
            unsigned int bh[4][2];
            #pragma unroll
            for (int nb2 = 0; nb2 < 2; nb2++) {
                unsigned int off = (rB + nb2 * 16) * 128 + cB + kc * 32;
                unsigned int sw = off ^ ((off >> 3) & 0x70);
                unsigned int r0, r1, r2, r3;
                LDSM4(r0, r1, r2, r3, stb + 32768 + sw);
                bh[2*nb2][0] = r0; bh[2*nb2][1] = r1;
                bh[2*nb2+1][0] = r2; bh[2*nb2+1][1] = r3;
            }
            #pragma unroll
            for (int mbl = 0; mbl < 4; mbl++)
                #pragma unroll
                for (int nbl = 0; nbl < 4; nbl++) {
                    MMA_F16(acc[mbl][nbl], ah[mbl], bh[nbl]);   // hi*B
                    MMA_F16(acc[mbl][nbl], al[mbl], bh[nbl]);   // lo*B
                }
        }
    }

    #pragma unroll
    for (int mbl = 0; mbl < 4; mbl++) {
        int mrow = row0 + warp_m * 64 + mbl * 16 + (lane >> 2);
        #pragma unroll
        for (int nbl = 0; nbl < 4; nbl++) {
            int ncol = col0 + warp_n * 32 + nbl * 8 + (lane & 3) * 2;
            float2 v0 = make_float2(acc[mbl][nbl][0], acc[mbl][nbl][1]);
            float2 v1 = make_float2(acc[mbl][nbl][2], acc[mbl][nbl][3]);
            *(float2*)&C[(size_t)mrow * DIM + ncol]       = v0;
            *(float2*)&C[(size_t)(mrow + 8) * DIM + ncol] = v1;
        }
    }
}

// ---------------------------------------------------------------------------
// RoPE + fp16: q split (hi/lo, prescaled), k rounded -> f16x2 words.
// ---------------------------------------------------------------------------
__global__ void __launch_bounds__(256) rope_split_kernel(
    const float* __restrict__ q, const float* __restrict__ k,
    const int* __restrict__ xyz,
    unsigned int* __restrict__ qhi, unsigned int* __restrict__ qlo,
    unsigned int* __restrict__ khi)
{
    int idx = blockIdx.x * 256 + threadIdx.x;   // NTOK*16*3*8
    int j2 = idx & 7;
    int p  = (idx >> 3) % 3;
    int th = idx / 24;
    int h  = th & 15;
    int t  = th >> 4;
    if (t >= NTOK) return;

    float pos = (float)xyz[t * 3 + p];
    const float c = 0.83048202372184058696f;   // log2(10000)/16
    int j0 = 2 * j2;
    float s0, c0, s1, c1;
    sincosf(pos * exp2f(-(float)j0 * c), &s0, &c0);
    sincosf(pos * exp2f(-(float)(j0 + 1) * c), &s1, &c1);

    int base = t * DIM + h * HD + p * 32 + j0;
    int wbase = t * (DIM/2) + h * (HD/2) + p * 16 + j2;

    {
        float2 a = *(const float2*)&q[base];
        float2 b = *(const float2*)&q[base + 16];
        float o1x = (a.x * c0 - b.x * s0) * ATT_SCALE;
        float o1y = (a.y * c1 - b.y * s1) * ATT_SCALE;
        float o2x = (b.x * c0 + a.x * s0) * ATT_SCALE;
        float o2y = (b.y * c1 + a.y * s1) * ATT_SCALE;
        unsigned int h1 = pack_f16x2(o1x, o1y);
        unsigned int h2 = pack_f16x2(o2x, o2y);
        unsigned int l1 = pack_f16x2(o1x - f16x2_lo(h1), o1y - f16x2_hi(h1));
        unsigned int l2 = pack_f16x2(o2x - f16x2_lo(h2), o2y - f16x2_hi(h2));
        qhi[wbase] = h1; qhi[wbase + 8] = h2;
        qlo[wbase] = l1; qlo[wbase + 8] = l2;
    }
    {
        float2 a = *(const float2*)&k[base];
        float2 b = *(const float2*)&k[base + 16];
        float o1x = a.x * c0 - b.x * s0;
        float o1y = a.y * c1 - b.y * s1;
        float o2x = b.x * c0 + a.x * s0;
        float o2y = b.y * c1 + a.y * s1;
        khi[wbase]     = pack_f16x2(o1x, o1y);
        khi[wbase + 8] = pack_f16x2(o2x, o2y);
    }
}

// ---------------------------------------------------------------------------
// V transpose + fp16 round
// ---------------------------------------------------------------------------
__global__ void __launch_bounds__(128) vtrans_kernel(
    const float* __restrict__ v, unsigned int* __restrict__ vthi)
{
    __shared__ float sm[96 * 65];
    const int tid = threadIdx.x;
    const int bh = blockIdx.y;
    const int b = bh >> 4, h = bh & 15;
    const int s0 = blockIdx.x * 64;

    {
        int s = tid >> 1, half = tid & 1;
        const float* src = v + (size_t)(b * SS + s0 + s) * DIM + h * HD + half * 48;
        #pragma unroll
        for (int i = 0; i < 12; i++) {
            float4 x = *(const float4*)(src + i * 4);
            int d = half * 48 + i * 4;
            sm[(d + 0) * 65 + s] = x.x;
            sm[(d + 1) * 65 + s] = x.y;
            sm[(d + 2) * 65 + s] = x.z;
            sm[(d + 3) * 65 + s] = x.w;
        }
    }
    __syncthreads();

    #pragma unroll
    for (int i = 0; i < 24; i++) {
        int w = tid + 128 * i;
        int d = w >> 5, j = w & 31;
        float f0 = sm[d * 65 + 2 * j];
        float f1 = sm[d * 65 + 2 * j + 1];
        vthi[(size_t)(bh * 96 + d) * 1024 + (s0 >> 1) + j] = pack_f16x2(f0, f1);
    }
}

// ---------------------------------------------------------------------------
// MMA flash attention (fp16: Q/P split, K/V rounded).
// Smem/buffer: KHI [64][52] words, VHI [96][36] words.
// ---------------------------------------------------------------------------
#define AKHI 0
#define AVHI 3328
#define ABUF 6784
#define ATT_SMEM_BYTES (2 * ABUF * 4)

__global__ void __launch_bounds__(128, 2) attn_mma_kernel(
    const unsigned int* __restrict__ qhi, const unsigned int* __restrict__ qlo,
    const unsigned int* __restrict__ khi,
    const unsigned int* __restrict__ vthi,
    unsigned int* __restrict__ aohi, unsigned int* __restrict__ aolo)
{
    extern __shared__ unsigned int smw[];
    unsigned int sbase = smem_u32(smw);

    const int tid  = threadIdx.x;
    const int lane = tid & 31;
    const int warp = tid >> 5;
    const int qt = blockIdx.x;
    const int bh = blockIdx.y;
    const int b = bh >> 4, h = bh & 15;
    const int h48 = h * 48;
    const int qrow0 = b * SS + qt * 64;

    unsigned int qh[6][4], ql[6][4];
    {
        const unsigned int* qhg = qhi + (size_t)qrow0 * 768 + h48;
        const unsigned int* qlg = qlo + (size_t)qrow0 * 768 + h48;
        int r0 = warp * 16 + (lane >> 2);
        #pragma unroll
        for (int kb = 0; kb < 6; kb++) {
            int w0 = kb * 8 + (lane & 3);
            qh[kb][0] = qhg[(size_t)r0 * 768 + w0];
            qh[kb][1] = qhg[(size_t)(r0 + 8) * 768 + w0];
            qh[kb][2] = qhg[(size_t)r0 * 768 + w0 + 4];
            qh[kb][3] = qhg[(size_t)(r0 + 8) * 768 + w0 + 4];
            ql[kb][0] = qlg[(size_t)r0 * 768 + w0];
            ql[kb][1] = qlg[(size_t)(r0 + 8) * 768 + w0];
            ql[kb][2] = qlg[(size_t)r0 * 768 + w0 + 4];
            ql[kb][3] = qlg[(size_t)(r0 + 8) * 768 + w0 + 4];
        }
    }

    float O[12][4];
    #pragma unroll
    for (int nb = 0; nb < 12; nb++)
        #pragma unroll
        for (int i = 0; i < 4; i++) O[nb][i] = 0.0f;
    float m0 = -CUDART_INF_F, m1 = -CUDART_INF_F, l0 = 0.0f, l1 = 0.0f;

#define PREFETCH(bi, ktv)                                                      \
    {                                                                          \
        int ktok = b * SS + (ktv) * 64;                                        \
        _Pragma("unroll")                                                      \
        for (int i = 0; i < 6; i++) {                                          \
            int cc = tid + 128 * i;                                            \
            int key = cc / 12, j = cc - key * 12;                              \
            unsigned int dw = ((bi) * ABUF + key * 52 + j * 4);                \
            CPA16(sbase + dw * 4,                                              \
                  khi + (size_t)(ktok + key) * 768 + h48 + j * 4);             \
        }                                                                      \
        _Pragma("unroll")                                                      \
        for (int i = 0; i < 6; i++) {                                          \
            int cc = tid + 128 * i;                                            \
            int d = cc >> 3, j = cc & 7;                                       \
            unsigned int dw = ((bi) * ABUF + AVHI + d * 36 + j * 4);           \
            CPA16(sbase + dw * 4,                                              \
                  vthi + (size_t)(bh * 96 + d) * 1024 + (ktv) * 32 + j * 4);   \
        }                                                                      \
        CP_COMMIT();                                                           \
    }

    PREFETCH(0, 0);

    for (int kt = 0; kt < SS / 64; kt++) {
        CP_WAIT0();
        __syncthreads();
        if (kt + 1 < SS / 64) PREFETCH((kt + 1) & 1, kt + 1);

        const unsigned int* kh = smw + (kt & 1) * ABUF + AKHI;
        const unsigned int* vh = smw + (kt & 1) * ABUF + AVHI;

        float S[8][4];
        #pragma unroll
        for (int nb = 0; nb < 8; nb++) {
            #pragma unroll
            for (int i = 0; i < 4; i++) S[nb][i] = 0.0f;
            int key = nb * 8 + (lane >> 2);
            #pragma unroll
            for (int kb = 0; kb < 6; kb++) {
                int w0 = kb * 8 + (lane & 3);
                unsigned int bhf[2] = { kh[key * 52 + w0], kh[key * 52 + w0 + 4] };
                MMA_F16(S[nb], qh[kb], bhf);
                MMA_F16(S[nb], ql[kb], bhf);
            }
        }

        float ml0 = -CUDART_INF_F, ml1 = -CUDART_INF_F;
        #pragma unroll
        for (int nb = 0; nb < 8; nb++) {
            ml0 = fmaxf(ml0, fmaxf(S[nb][0], S[nb][1]));
            ml1 = fmaxf(ml1, fmaxf(S[nb][2], S[nb][3]));
        }
        ml0 = fmaxf(ml0, __shfl_xor_sync(0xffffffffu, ml0, 1));
        ml0 = fmaxf(ml0, __shfl_xor_sync(0xffffffffu, ml0, 2));
        ml1 = fmaxf(ml1, __shfl_xor_sync(0xffffffffu, ml1, 1));
        ml1 = fmaxf(ml1, __shfl_xor_sync(0xffffffffu, ml1, 2));
        float mn0 = fmaxf(m0, ml0), mn1 = fmaxf(m1, ml1);
        float sc0 = __expf(m0 - mn0), sc1 = __expf(m1 - mn1);
        float r0 = 0.0f, r1 = 0.0f;
        #pragma unroll
        for (int nb = 0; nb < 8; nb++) {
            S[nb][0] = __expf(S[nb][0] - mn0);
            S[nb][1] = __expf(S[nb][1] - mn0);
            S[nb][2] = __expf(S[nb][2] - mn1);
            S[nb][3] = __expf(S[nb][3] - mn1);
            r0 += S[nb][0] + S[nb][1];
            r1 += S[nb][2] + S[nb][3];
        }
        r0 += __shfl_xor_sync(0xffffffffu, r0, 1);
        r0 += __shfl_xor_sync(0xffffffffu, r0, 2);
        r1 += __shfl_xor_sync(0xffffffffu, r1, 1);
        r1 += __shfl_xor_sync(0xffffffffu, r1, 2);
        l0 = l0 * sc0 + r0;  m0 = mn0;
        l1 = l1 * sc1 + r1;  m1 = mn1;

        #pragma unroll
        for (int nb = 0; nb < 12; nb++) {
            O[nb][0] *= sc0; O[nb][1] *= sc0;
            O[nb][2] *= sc1; O[nb][3] *= sc1;
        }

        // P: C-frag -> fp16 A-frag (hi + lo residual)
        unsigned int ph[4][4], pl[4][4];
        #pragma unroll
        for (int kb = 0; kb < 4; kb++) {
            float f[8] = { S[2*kb][0], S[2*kb][1], S[2*kb][2], S[2*kb][3],
                           S[2*kb+1][0], S[2*kb+1][1], S[2*kb+1][2], S[2*kb+1][3] };
            #pragma unroll
            for (int rgp = 0; rgp < 4; rgp++) {
                unsigned int hw = pack_f16x2(f[2*rgp], f[2*rgp+1]);
                ph[kb][rgp] = hw;
                pl[kb][rgp] = pack_f16x2(f[2*rgp]   - f16x2_lo(hw),
                                         f[2*rgp+1] - f16x2_hi(hw));
            }
        }

        #pragma unroll
        for (int nb = 0; nb < 12; nb++) {
            int d = nb * 8 + (lane >> 2);
            #pragma unroll
            for (int kb = 0; kb < 4; kb++) {
                int w0 = kb * 8 + (lane & 3);
                unsigned int bhf[2] = { vh[d * 36 + w0], vh[d * 36 + w0 + 4] };
                MMA_F16(O[nb], ph[kb], bhf);
                MMA_F16(O[nb], pl[kb], bhf);
            }
        }
    }

    float li0 = 1.0f / l0, li1 = 1.0f / l1;
    int tok0 = qrow0 + warp * 16 + (lane >> 2);
    int tok1 = tok0 + 8;
    #pragma unroll
    for (int nb = 0; nb < 12; nb++) {
        int wd = nb * 4 + (lane & 3);
        float c0 = O[nb][0] * li0, c1 = O[nb][1] * li0;
        float c2 = O[nb][2] * li1, c3 = O[nb][3] * li1;
        unsigned int hw0 = pack_f16x2(c0, c1);
        unsigned int lw0 = pack_f16x2(c0 - f16x2_lo(hw0), c1 - f16x2_hi(hw0));
        unsigned int hw1 = pack_f16x2(c2, c3);
        unsigned int lw1 = pack_f16x2(c2 - f16x2_lo(hw1), c3 - f16x2_hi(hw1));
        aohi[(size_t)tok0 * 768 + h48 + wd] = hw0;
        aolo[(size_t)tok0 * 768 + h48 + wd] = lw0;
        aohi[(size_t)tok1 * 768 + h48 + wd] = hw1;
        aolo[(size_t)tok1 * 768 + h48 + wd] = lw1;
    }
}

// ---------------------------------------------------------------------------
extern "C" void kernel_launch(void* const* d_in, const int* in_sizes, int n_in,
                              void* d_out, int out_size)
{
    const int*   xyz = (const int*)d_in[0];
    const float* h   = (const float*)d_in[1];
    const float* wq  = (const float*)d_in[2];
    const float* wk  = (const float*)d_in[3];
    const float* wv  = (const float*)d_in[4];
    const float* wo  = (const float*)d_in[5];
    float* out = (float*)d_out;

    float *pq, *pk, *pv;
    cudaGetSymbolAddress((void**)&pq,  g_q);
    cudaGetSymbolAddress((void**)&pk,  g_k);
    cudaGetSymbolAddress((void**)&pv,  g_v);

    __half *hh, *hl, *aoh, *aol, *wqh, *wkh, *wvh, *woh;
    cudaGetSymbolAddress((void**)&hh,  g_h_hi);  cudaGetSymbolAddress((void**)&hl,  g_h_lo);
    cudaGetSymbolAddress((void**)&aoh, g_ao_hi); cudaGetSymbolAddress((void**)&aol, g_ao_lo);
    cudaGetSymbolAddress((void**)&wqh, g_wq_hi);
    cudaGetSymbolAddress((void**)&wkh, g_wk_hi);
    cudaGetSymbolAddress((void**)&wvh, g_wv_hi);
    cudaGetSymbolAddress((void**)&woh, g_wo_hi);

    unsigned int *uqh, *uql, *ukh, *uvh;
    cudaGetSymbolAddress((void**)&uqh, g_qhi);  cudaGetSymbolAddress((void**)&uql, g_qlo);
    cudaGetSymbolAddress((void**)&ukh, g_khi);
    cudaGetSymbolAddress((void**)&uvh, g_vthi);

    const int nH4 = NTOK * DIM / 4;
    const int nW4 = DIM * DIM / 4;
    split_fp16_kernel<<<(nH4 + 255)/256, 256>>>((const float4*)h,
        (unsigned int*)hh, (unsigned int*)hl, nH4);
    round_fp16_kernel<<<(nW4 + 255)/256, 256>>>((const float4*)wq, (unsigned int*)wqh, nW4);
    round_fp16_kernel<<<(nW4 + 255)/256, 256>>>((const float4*)wk, (unsigned int*)wkh, nW4);
    round_fp16_kernel<<<(nW4 + 255)/256, 256>>>((const float4*)wv, (unsigned int*)wvh, nW4);
    round_fp16_kernel<<<(nW4 + 255)/256, 256>>>((const float4*)wo, (unsigned int*)woh, nW4);

    cudaFuncSetAttribute(gemm_ldsm_nt, cudaFuncAttributeMaxDynamicSharedMemorySize, GL_SMEM);

    // fused QKV projections
    GemmPtrs Pqkv;
    Pqkv.b0 = wqh; Pqkv.b1 = wkh; Pqkv.b2 = wvh;
    Pqkv.c0 = pq;  Pqkv.c1 = pk;  Pqkv.c2 = pv;
    dim3 gq(DIM / 128, NTOK / 128, 3);   // (12, 32, 3)
    gemm_ldsm_nt<<<gq, 256, GL_SMEM>>>(hh, hl, Pqkv);

    int rope_threads = NTOK * NHD * 3 * 8;
    rope_split_kernel<<<rope_threads / 256, 256>>>(pq, pk, xyz, uqh, uql, ukh);

    dim3 vgrid(SS / 64, BB * NHD);
    vtrans_kernel<<<vgrid, 128>>>(pv, uvh);

    cudaFuncSetAttribute(attn_mma_kernel, cudaFuncAttributeMaxDynamicSharedMemorySize, ATT_SMEM_BYTES);
    dim3 agrid(SS / 64, BB * NHD);
    attn_mma_kernel<<<agrid, 128, ATT_SMEM_BYTES>>>(
        uqh, uql, ukh, uvh, (unsigned int*)aoh, (unsigned int*)aol);

    // O projection
    GemmPtrs Po;
    Po.b0 = woh; Po.b1 = woh; Po.b2 = woh;
    Po.c0 = out; Po.c1 = out; Po.c2 = out;
    dim3 go(DIM / 128, NTOK / 128, 1);
    gemm_ldsm_nt<<<go, 256, GL_SMEM>>>(aoh, aol, Po);
}

// round 9
// speedup vs baseline: 5.7835x; 1.0343x over previous
#include <cuda_runtime.h>
#include <cuda_fp16.h>
#include <math_constants.h>
#include <cstdint>

// Problem constants
#define BB   2
#define SS   2048
#define DIM  1536
#define NHD  16
#define HD   96
#define NTOK (BB*SS)            // 4096
#define ATT_SCALE 0.10206207261596575f   // 1/sqrt(96)

// Scratch (device globals; allocation-free)
__device__ float g_q[NTOK * DIM];
__device__ float g_k[NTOK * DIM];
__device__ float g_v[NTOK * DIM];

__device__ __half g_h_hi[NTOK * DIM],  g_h_lo[NTOK * DIM];
__device__ __half g_ao_hi[NTOK * DIM];
__device__ __half g_wq_hi[DIM * DIM];
__device__ __half g_wk_hi[DIM * DIM];
__device__ __half g_wv_hi[DIM * DIM];
__device__ __half g_wo_hi[DIM * DIM];

// Post-RoPE fp16 (q split + prescaled by ATT_SCALE; k rounded), f16x2 words
__device__ unsigned int g_qhi[NTOK * DIM / 2], g_qlo[NTOK * DIM / 2];
__device__ unsigned int g_khi[NTOK * DIM / 2];
// V transposed per (b,h): [32][96][2048] fp16 -> words [32][96][1024]
__device__ unsigned int g_vthi[32 * 96 * 1024];

// ---------------------------------------------------------------------------
// helpers
// ---------------------------------------------------------------------------
__device__ __forceinline__ unsigned int pack_f16x2(float lo, float hi) {
    unsigned int r;
    asm("cvt.rn.f16x2.f32 %0, %1, %2;" : "=r"(r) : "f"(hi), "f"(lo));
    return r;
}
__device__ __forceinline__ float f16x2_lo(unsigned int w) {
    float f;
    asm("{ .reg .b16 l, h; mov.b32 {l, h}, %1; cvt.f32.f16 %0, l; }" : "=f"(f) : "r"(w));
    return f;
}
__device__ __forceinline__ float f16x2_hi(unsigned int w) {
    float f;
    asm("{ .reg .b16 l, h; mov.b32 {l, h}, %1; cvt.f32.f16 %0, h; }" : "=f"(f) : "r"(w));
    return f;
}
__device__ __forceinline__ unsigned int smem_u32(const void* p) {
    unsigned int a;
    asm("{ .reg .u64 t; cvta.to.shared.u64 t, %1; cvt.u32.u64 %0, t; }"
        : "=r"(a) : "l"(p));
    return a;
}

#define MMA_F16(d, a, b) \
  asm volatile("mma.sync.aligned.m16n8k16.row.col.f32.f16.f16.f32 " \
    "{%0,%1,%2,%3}, {%4,%5,%6,%7}, {%8,%9}, {%0,%1,%2,%3};" \
    : "+f"(d[0]), "+f"(d[1]), "+f"(d[2]), "+f"(d[3]) \
    : "r"(a[0]), "r"(a[1]), "r"(a[2]), "r"(a[3]), "r"(b[0]), "r"(b[1]))

#define LDSM4(r0, r1, r2, r3, addr) \
  asm volatile("ldmatrix.sync.aligned.m8n8.x4.shared.b16 {%0,%1,%2,%3}, [%4];" \
    : "=r"(r0), "=r"(r1), "=r"(r2), "=r"(r3) : "r"(addr))

#define CPA16(dst_s, src_g) \
  asm volatile("cp.async.ca.shared.global [%0], [%1], 16;" :: "r"(dst_s), "l"(src_g))
#define CPA16CG(dst_s, src_g) \
  asm volatile("cp.async.cg.shared.global [%0], [%1], 16;" :: "r"(dst_s), "l"(src_g))
#define CP_COMMIT() asm volatile("cp.async.commit_group;" ::: "memory")
#define CP_WAIT0()  asm volatile("cp.async.wait_group 0;" ::: "memory")

// ---------------------------------------------------------------------------
// fp32 -> (fp16 hi, fp16 lo) split. n multiple of 4.
// ---------------------------------------------------------------------------
__global__ void __launch_bounds__(256) split_fp16_kernel(
    const float4* __restrict__ x, unsigned int* __restrict__ hi,
    unsigned int* __restrict__ lo, int n4)
{
    int i = blockIdx.x * 256 + threadIdx.x;
    if (i >= n4) return;
    float4 v = x[i];
    unsigned int h0 = pack_f16x2(v.x, v.y);
    unsigned int h1 = pack_f16x2(v.z, v.w);
    unsigned int l0 = pack_f16x2(v.x - f16x2_lo(h0), v.y - f16x2_hi(h0));
    unsigned int l1 = pack_f16x2(v.z - f16x2_lo(h1), v.w - f16x2_hi(h1));
    hi[i*2] = h0; hi[i*2+1] = h1;
    lo[i*2] = l0; lo[i*2+1] = l1;
}

// fp32 -> fp16 round
__global__ void __launch_bounds__(256) round_fp16_kernel(
    const float4* __restrict__ x, unsigned int* __restrict__ hi, int n4)
{
    int i = blockIdx.x * 256 + threadIdx.x;
    if (i >= n4) return;
    float4 v = x[i];
    hi[i*2]   = pack_f16x2(v.x, v.y);
    hi[i*2+1] = pack_f16x2(v.z, v.w);
}

// ---------------------------------------------------------------------------
// ldmatrix tensor-core GEMM: C[m][n] = sum_k A[m][k] * W[n][k]
// CTA 128x128, BK=64, 256 threads, warp 64x32. split_mask bit z: A split hi+lo
// (2 MMAs) vs hi-only (1 MMA). grid.z = QKV fusion.
// ---------------------------------------------------------------------------
#define GL_STAGE 49152     // 3 tiles x 128 rows x 128B (Ahi, Alo, Bhi)
#define GL_SMEM  (2 * GL_STAGE)
#define GL_NC    (DIM / 64)   // 24

struct GemmPtrs {
    const __half *b0, *b1, *b2;
    float *c0, *c1, *c2;
    int split_mask;
};

__device__ __forceinline__ void gl_prefetch(
    unsigned int stage_base,
    const __half* __restrict__ a_h, const __half* __restrict__ a_l,
    const __half* __restrict__ b_h,
    int tid, int koff, bool with_lo)
{
    #pragma unroll
    for (int t = 0; t < 3; t++) {
        if (t == 1 && !with_lo) continue;
        const __half* s = (t == 0) ? a_h : (t == 1) ? a_l : b_h;
        #pragma unroll
        for (int i = 0; i < 4; i++) {
            int w = tid + 256 * i;          // 0..1023
            int r = w >> 3, cc = w & 7;     // row, 16B chunk
            unsigned int off = r * 128 + cc * 16;
            unsigned int dst = stage_base + t * 16384 + (off ^ ((off >> 3) & 0x70));
            CPA16CG(dst, s + (size_t)r * DIM + koff + cc * 8);
        }
    }
    CP_COMMIT();
}

__global__ void __launch_bounds__(256, 2) gemm_ldsm_nt(
    const __half* __restrict__ Ahi, const __half* __restrict__ Alo,
    GemmPtrs P)
{
    extern __shared__ char smraw[];
    const unsigned int sbase = smem_u32(smraw);
    const int tid  = threadIdx.x;
    const int lane = tid & 31;
    const int warp = tid >> 5;
    const int warp_m = warp >> 2;    // 0..1
    const int warp_n = warp & 3;     // 0..3
    const int row0 = blockIdx.y * 128;
    const int col0 = blockIdx.x * 128;
    const int z = blockIdx.z;
    const bool use_lo = (P.split_mask >> z) & 1;

    const __half* Whi = (z == 0) ? P.b0 : (z == 1) ? P.b1 : P.b2;
    float* C = (z == 0) ? P.c0 : (z == 1) ? P.c1 : P.c2;

    const __half* a_h = Ahi + (size_t)row0 * DIM;
    const __half* a_l = Alo + (size_t)row0 * DIM;
    const __half* b_h = Whi + (size_t)col0 * DIM;

    // ldmatrix lane address components
    const int g = lane >> 3, j = lane & 7;
    const unsigned int rA = warp_m * 64 + (g & 1) * 8 + j;   // + mbl*16
    const unsigned int cA = (g >> 1) * 16;                   // + kc*32
    const unsigned int rB = warp_n * 32 + (g >> 1) * 8 + j;  // + nb2*16
    const unsigned int cB = (g & 1) * 16;

    float acc[4][4][4] = {};    // [mbl][nbl][reg]

    gl_prefetch(sbase, a_h, a_l, b_h, tid, 0, use_lo);

    for (int c = 0; c < GL_NC; c++) {
        CP_WAIT0();
        __syncthreads();
        if (c + 1 < GL_NC)
            gl_prefetch(sbase + ((c + 1) & 1) * GL_STAGE, a_h, a_l, b_h,
                        tid, (c + 1) * 64, use_lo);

        const unsigned int stb = sbase + (c & 1) * GL_STAGE;

        #pragma unroll
        for (int kc = 0; kc < 4; kc++) {
            unsigned int ah[4][4], al[4][4];
            #pragma unroll
            for (int mbl = 0; mbl < 4; mbl++) {
                unsigned int off = (rA + mbl * 16) * 128 + cA + kc * 32;
                unsigned int sw = off ^ ((off >> 3) & 0x70);
                LDSM4(ah[mbl][0], ah[mbl][1], ah[mbl][2], ah[mbl][3], stb + sw);
                if (use_lo)
                    LDSM4(al[mbl][0], al[mbl][1], al[mbl][2], al[mbl][3],
                          stb + 16384 + sw);
            }
            unsigned int bh[4][2];
            #pragma unroll
            for (int nb2 = 0; nb2 < 2; nb2++) {
                unsigned int off = (rB + nb2 * 16) * 128 + cB + kc * 32;
                unsigned int sw = off ^ ((off >> 3) & 0x70);
                unsigned int r0, r1, r2, r3;
                LDSM4(r0, r1, r2, r3, stb + 32768 + sw);
                bh[2*nb2][0] = r0; bh[2*nb2][1] = r1;
                bh[2*nb2+1][0] = r2; bh[2*nb2+1][1] = r3;
            }
            #pragma unroll
            for (int mbl = 0; mbl < 4; mbl++)
                #pragma unroll
                for (int nbl = 0; nbl < 4; nbl++) {
                    MMA_F16(acc[mbl][nbl], ah[mbl], bh[nbl]);       // hi*B
                    if (use_lo)
                        MMA_F16(acc[mbl][nbl], al[mbl], bh[nbl]);   // lo*B
                }
        }
    }

    #pragma unroll
    for (int mbl = 0; mbl < 4; mbl++) {
        int mrow = row0 + warp_m * 64 + mbl * 16 + (lane >> 2);
        #pragma unroll
        for (int nbl = 0; nbl < 4; nbl++) {
            int ncol = col0 + warp_n * 32 + nbl * 8 + (lane & 3) * 2;
            float2 v0 = make_float2(acc[mbl][nbl][0], acc[mbl][nbl][1]);
            float2 v1 = make_float2(acc[mbl][nbl][2], acc[mbl][nbl][3]);
            *(float2*)&C[(size_t)mrow * DIM + ncol]       = v0;
            *(float2*)&C[(size_t)(mrow + 8) * DIM + ncol] = v1;
        }
    }
}

// ---------------------------------------------------------------------------
// RoPE + fp16: q split (hi/lo, prescaled), k rounded -> f16x2 words.
// ---------------------------------------------------------------------------
__global__ void __launch_bounds__(256) rope_split_kernel(
    const float* __restrict__ q, const float* __restrict__ k,
    const int* __restrict__ xyz,
    unsigned int* __restrict__ qhi, unsigned int* __restrict__ qlo,
    unsigned int* __restrict__ khi)
{
    int idx = blockIdx.x * 256 + threadIdx.x;   // NTOK*16*3*8
    int j2 = idx & 7;
    int p  = (idx >> 3) % 3;
    int th = idx / 24;
    int h  = th & 15;
    int t  = th >> 4;
    if (t >= NTOK) return;

    float pos = (float)xyz[t * 3 + p];
    const float c = 0.83048202372184058696f;   // log2(10000)/16
    int j0 = 2 * j2;
    float s0, c0, s1, c1;
    sincosf(pos * exp2f(-(float)j0 * c), &s0, &c0);
    sincosf(pos * exp2f(-(float)(j0 + 1) * c), &s1, &c1);

    int base = t * DIM + h * HD + p * 32 + j0;
    int wbase = t * (DIM/2) + h * (HD/2) + p * 16 + j2;

    {
        float2 a = *(const float2*)&q[base];
        float2 b = *(const float2*)&q[base + 16];
        float o1x = (a.x * c0 - b.x * s0) * ATT_SCALE;
        float o1y = (a.y * c1 - b.y * s1) * ATT_SCALE;
        float o2x = (b.x * c0 + a.x * s0) * ATT_SCALE;
        float o2y = (b.y * c1 + a.y * s1) * ATT_SCALE;
        unsigned int h1 = pack_f16x2(o1x, o1y);
        unsigned int h2 = pack_f16x2(o2x, o2y);
        unsigned int l1 = pack_f16x2(o1x - f16x2_lo(h1), o1y - f16x2_hi(h1));
        unsigned int l2 = pack_f16x2(o2x - f16x2_lo(h2), o2y - f16x2_hi(h2));
        qhi[wbase] = h1; qhi[wbase + 8] = h2;
        qlo[wbase] = l1; qlo[wbase + 8] = l2;
    }
    {
        float2 a = *(const float2*)&k[base];
        float2 b = *(const float2*)&k[base + 16];
        float o1x = a.x * c0 - b.x * s0;
        float o1y = a.y * c1 - b.y * s1;
        float o2x = b.x * c0 + a.x * s0;
        float o2y = b.y * c1 + a.y * s1;
        khi[wbase]     = pack_f16x2(o1x, o1y);
        khi[wbase + 8] = pack_f16x2(o2x, o2y);
    }
}

// ---------------------------------------------------------------------------
// V transpose + fp16 round
// ---------------------------------------------------------------------------
__global__ void __launch_bounds__(128) vtrans_kernel(
    const float* __restrict__ v, unsigned int* __restrict__ vthi)
{
    __shared__ float sm[96 * 65];
    const int tid = threadIdx.x;
    const int bh = blockIdx.y;
    const int b = bh >> 4, h = bh & 15;
    const int s0 = blockIdx.x * 64;

    {
        int s = tid >> 1, half = tid & 1;
        const float* src = v + (size_t)(b * SS + s0 + s) * DIM + h * HD + half * 48;
        #pragma unroll
        for (int i = 0; i < 12; i++) {
            float4 x = *(const float4*)(src + i * 4);
            int d = half * 48 + i * 4;
            sm[(d + 0) * 65 + s] = x.x;
            sm[(d + 1) * 65 + s] = x.y;
            sm[(d + 2) * 65 + s] = x.z;
            sm[(d + 3) * 65 + s] = x.w;
        }
    }
    __syncthreads();

    #pragma unroll
    for (int i = 0; i < 24; i++) {
        int w = tid + 128 * i;
        int d = w >> 5, j = w & 31;
        float f0 = sm[d * 65 + 2 * j];
        float f1 = sm[d * 65 + 2 * j + 1];
        vthi[(size_t)(bh * 96 + d) * 1024 + (s0 >> 1) + j] = pack_f16x2(f0, f1);
    }
}

// ---------------------------------------------------------------------------
// MMA flash attention (fp16: Q/P split, K/V rounded). Output: aohi only.
// Smem/buffer: KHI [64][52] words, VHI [96][36] words.
// ---------------------------------------------------------------------------
#define AKHI 0
#define AVHI 3328
#define ABUF 6784
#define ATT_SMEM_BYTES (2 * ABUF * 4)

__global__ void __launch_bounds__(128, 2) attn_mma_kernel(
    const unsigned int* __restrict__ qhi, const unsigned int* __restrict__ qlo,
    const unsigned int* __restrict__ khi,
    const unsigned int* __restrict__ vthi,
    unsigned int* __restrict__ aohi)
{
    extern __shared__ unsigned int smw[];
    unsigned int sbase = smem_u32(smw);

    const int tid  = threadIdx.x;
    const int lane = tid & 31;
    const int warp = tid >> 5;
    const int qt = blockIdx.x;
    const int bh = blockIdx.y;
    const int b = bh >> 4, h = bh & 15;
    const int h48 = h * 48;
    const int qrow0 = b * SS + qt * 64;

    unsigned int qh[6][4], ql[6][4];
    {
        const unsigned int* qhg = qhi + (size_t)qrow0 * 768 + h48;
        const unsigned int* qlg = qlo + (size_t)qrow0 * 768 + h48;
        int r0 = warp * 16 + (lane >> 2);
        #pragma unroll
        for (int kb = 0; kb < 6; kb++) {
            int w0 = kb * 8 + (lane & 3);
            qh[kb][0] = qhg[(size_t)r0 * 768 + w0];
            qh[kb][1] = qhg[(size_t)(r0 + 8) * 768 + w0];
            qh[kb][2] = qhg[(size_t)r0 * 768 + w0 + 4];
            qh[kb][3] = qhg[(size_t)(r0 + 8) * 768 + w0 + 4];
            ql[kb][0] = qlg[(size_t)r0 * 768 + w0];
            ql[kb][1] = qlg[(size_t)(r0 + 8) * 768 + w0];
            ql[kb][2] = qlg[(size_t)r0 * 768 + w0 + 4];
            ql[kb][3] = qlg[(size_t)(r0 + 8) * 768 + w0 + 4];
        }
    }

    float O[12][4];
    #pragma unroll
    for (int nb = 0; nb < 12; nb++)
        #pragma unroll
        for (int i = 0; i < 4; i++) O[nb][i] = 0.0f;
    float m0 = -CUDART_INF_F, m1 = -CUDART_INF_F, l0 = 0.0f, l1 = 0.0f;

#define PREFETCH(bi, ktv)                                                      \
    {                                                                          \
        int ktok = b * SS + (ktv) * 64;                                        \
        _Pragma("unroll")                                                      \
        for (int i = 0; i < 6; i++) {                                          \
            int cc = tid + 128 * i;                                            \
            int key = cc / 12, j = cc - key * 12;                              \
            unsigned int dw = ((bi) * ABUF + key * 52 + j * 4);                \
            CPA16(sbase + dw * 4,                                              \
                  khi + (size_t)(ktok + key) * 768 + h48 + j * 4);             \
        }                                                                      \
        _Pragma("unroll")                                                      \
        for (int i = 0; i < 6; i++) {                                          \
            int cc = tid + 128 * i;                                            \
            int d = cc >> 3, j = cc & 7;                                       \
            unsigned int dw = ((bi) * ABUF + AVHI + d * 36 + j * 4);           \
            CPA16(sbase + dw * 4,                                              \
                  vthi + (size_t)(bh * 96 + d) * 1024 + (ktv) * 32 + j * 4);   \
        }                                                                      \
        CP_COMMIT();                                                           \
    }

    PREFETCH(0, 0);

    for (int kt = 0; kt < SS / 64; kt++) {
        CP_WAIT0();
        __syncthreads();
        if (kt + 1 < SS / 64) PREFETCH((kt + 1) & 1, kt + 1);

        const unsigned int* kh = smw + (kt & 1) * ABUF + AKHI;
        const unsigned int* vh = smw + (kt & 1) * ABUF + AVHI;

        float S[8][4];
        #pragma unroll
        for (int nb = 0; nb < 8; nb++) {
            #pragma unroll
            for (int i = 0; i < 4; i++) S[nb][i] = 0.0f;
            int key = nb * 8 + (lane >> 2);
            #pragma unroll
            for (int kb = 0; kb < 6; kb++) {
                int w0 = kb * 8 + (lane & 3);
                unsigned int bhf[2] = { kh[key * 52 + w0], kh[key * 52 + w0 + 4] };
                MMA_F16(S[nb], qh[kb], bhf);
                MMA_F16(S[nb], ql[kb], bhf);
            }
        }

        float ml0 = -CUDART_INF_F, ml1 = -CUDART_INF_F;
        #pragma unroll
        for (int nb = 0; nb < 8; nb++) {
            ml0 = fmaxf(ml0, fmaxf(S[nb][0], S[nb][1]));
            ml1 = fmaxf(ml1, fmaxf(S[nb][2], S[nb][3]));
        }
        ml0 = fmaxf(ml0, __shfl_xor_sync(0xffffffffu, ml0, 1));
        ml0 = fmaxf(ml0, __shfl_xor_sync(0xffffffffu, ml0, 2));
        ml1 = fmaxf(ml1, __shfl_xor_sync(0xffffffffu, ml1, 1));
        ml1 = fmaxf(ml1, __shfl_xor_sync(0xffffffffu, ml1, 2));
        float mn0 = fmaxf(m0, ml0), mn1 = fmaxf(m1, ml1);
        float sc0 = __expf(m0 - mn0), sc1 = __expf(m1 - mn1);
        float r0 = 0.0f, r1 = 0.0f;
        #pragma unroll
        for (int nb = 0; nb < 8; nb++) {
            S[nb][0] = __expf(S[nb][0] - mn0);
            S[nb][1] = __expf(S[nb][1] - mn0);
            S[nb][2] = __expf(S[nb][2] - mn1);
            S[nb][3] = __expf(S[nb][3] - mn1);
            r0 += S[nb][0] + S[nb][1];
            r1 += S[nb][2] + S[nb][3];
        }
        r0 += __shfl_xor_sync(0xffffffffu, r0, 1);
        r0 += __shfl_xor_sync(0xffffffffu, r0, 2);
        r1 += __shfl_xor_sync(0xffffffffu, r1, 1);
        r1 += __shfl_xor_sync(0xffffffffu, r1, 2);
        l0 = l0 * sc0 + r0;  m0 = mn0;
        l1 = l1 * sc1 + r1;  m1 = mn1;

        #pragma unroll
        for (int nb = 0; nb < 12; nb++) {
            O[nb][0] *= sc0; O[nb][1] *= sc0;
            O[nb][2] *= sc1; O[nb][3] *= sc1;
        }

        // P: C-frag -> fp16 A-frag (hi + lo residual)
        unsigned int ph[4][4], pl[4][4];
        #pragma unroll
        for (int kb = 0; kb < 4; kb++) {
            float f[8] = { S[2*kb][0], S[2*kb][1], S[2*kb][2], S[2*kb][3],
                           S[2*kb+1][0], S[2*kb+1][1], S[2*kb+1][2], S[2*kb+1][3] };
            #pragma unroll
            for (int rgp = 0; rgp < 4; rgp++) {
                unsigned int hw = pack_f16x2(f[2*rgp], f[2*rgp+1]);
                ph[kb][rgp] = hw;
                pl[kb][rgp] = pack_f16x2(f[2*rgp]   - f16x2_lo(hw),
                                         f[2*rgp+1] - f16x2_hi(hw));
            }
        }

        #pragma unroll
        for (int nb = 0; nb < 12; nb++) {
            int d = nb * 8 + (lane >> 2);
            #pragma unroll
            for (int kb = 0; kb < 4; kb++) {
                int w0 = kb * 8 + (lane & 3);
                unsigned int bhf[2] = { vh[d * 36 + w0], vh[d * 36 + w0 + 4] };
                MMA_F16(O[nb], ph[kb], bhf);
                MMA_F16(O[nb], pl[kb], bhf);
            }
        }
    }

    float li0 = 1.0f / l0, li1 = 1.0f / l1;
    int tok0 = qrow0 + warp * 16 + (lane >> 2);
    int tok1 = tok0 + 8;
    #pragma unroll
    for (int nb = 0; nb < 12; nb++) {
        int wd = nb * 4 + (lane & 3);
        aohi[(size_t)tok0 * 768 + h48 + wd] =
            pack_f16x2(O[nb][0] * li0, O[nb][1] * li0);
        aohi[(size_t)tok1 * 768 + h48 + wd] =
            pack_f16x2(O[nb][2] * li1, O[nb][3] * li1);
    }
}

// ---------------------------------------------------------------------------
extern "C" void kernel_launch(void* const* d_in, const int* in_sizes, int n_in,
                              void* d_out, int out_size)
{
    const int*   xyz = (const int*)d_in[0];
    const float* h   = (const float*)d_in[1];
    const float* wq  = (const float*)d_in[2];
    const float* wk  = (const float*)d_in[3];
    const float* wv  = (const float*)d_in[4];
    const float* wo  = (const float*)d_in[5];
    float* out = (float*)d_out;

    float *pq, *pk, *pv;
    cudaGetSymbolAddress((void**)&pq,  g_q);
    cudaGetSymbolAddress((void**)&pk,  g_k);
    cudaGetSymbolAddress((void**)&pv,  g_v);

    __half *hh, *hl, *aoh, *wqh, *wkh, *wvh, *woh;
    cudaGetSymbolAddress((void**)&hh,  g_h_hi);  cudaGetSymbolAddress((void**)&hl,  g_h_lo);
    cudaGetSymbolAddress((void**)&aoh, g_ao_hi);
    cudaGetSymbolAddress((void**)&wqh, g_wq_hi);
    cudaGetSymbolAddress((void**)&wkh, g_wk_hi);
    cudaGetSymbolAddress((void**)&wvh, g_wv_hi);
    cudaGetSymbolAddress((void**)&woh, g_wo_hi);

    unsigned int *uqh, *uql, *ukh, *uvh;
    cudaGetSymbolAddress((void**)&uqh, g_qhi);  cudaGetSymbolAddress((void**)&uql, g_qlo);
    cudaGetSymbolAddress((void**)&ukh, g_khi);
    cudaGetSymbolAddress((void**)&uvh, g_vthi);

    const int nH4 = NTOK * DIM / 4;
    const int nW4 = DIM * DIM / 4;
    split_fp16_kernel<<<(nH4 + 255)/256, 256>>>((const float4*)h,
        (unsigned int*)hh, (unsigned int*)hl, nH4);
    round_fp16_kernel<<<(nW4 + 255)/256, 256>>>((const float4*)wq, (unsigned int*)wqh, nW4);
    round_fp16_kernel<<<(nW4 + 255)/256, 256>>>((const float4*)wk, (unsigned int*)wkh, nW4);
    round_fp16_kernel<<<(nW4 + 255)/256, 256>>>((const float4*)wv, (unsigned int*)wvh, nW4);
    round_fp16_kernel<<<(nW4 + 255)/256, 256>>>((const float4*)wo, (unsigned int*)woh, nW4);

    cudaFuncSetAttribute(gemm_ldsm_nt, cudaFuncAttributeMaxDynamicSharedMemorySize, GL_SMEM);

    // fused QKV projections: Q split (bit0), K/V hi-only
    GemmPtrs Pqkv;
    Pqkv.b0 = wqh; Pqkv.b1 = wkh; Pqkv.b2 = wvh;
    Pqkv.c0 = pq;  Pqkv.c1 = pk;  Pqkv.c2 = pv;
    Pqkv.split_mask = 0x1;
    dim3 gq(DIM / 128, NTOK / 128, 3);   // (12, 32, 3)
    gemm_ldsm_nt<<<gq, 256, GL_SMEM>>>(hh, hl, Pqkv);

    int rope_threads = NTOK * NHD * 3 * 8;
    rope_split_kernel<<<rope_threads / 256, 256>>>(pq, pk, xyz, uqh, uql, ukh);

    dim3 vgrid(SS / 64, BB * NHD);
    vtrans_kernel<<<vgrid, 128>>>(pv, uvh);

    cudaFuncSetAttribute(attn_mma_kernel, cudaFuncAttributeMaxDynamicSharedMemorySize, ATT_SMEM_BYTES);
    dim3 agrid(SS / 64, BB * NHD);
    attn_mma_kernel<<<agrid, 128, ATT_SMEM_BYTES>>>(
        uqh, uql, ukh, uvh, (unsigned int*)aoh);

    // O projection: ao rounded (hi-only, 1 MMA)
    GemmPtrs Po;
    Po.b0 = woh; Po.b1 = woh; Po.b2 = woh;
    Po.c0 = out; Po.c1 = out; Po.c2 = out;
    Po.split_mask = 0x0;
    dim3 go(DIM / 128, NTOK / 128, 1);
    gemm_ldsm_nt<<<go, 256, GL_SMEM>>>(aoh, aoh, Po);
}

// round 10
// speedup vs baseline: 6.2788x; 1.0857x over previous
#include <cuda_runtime.h>
#include <cuda_fp16.h>
#include <math_constants.h>
#include <cstdint>

// Problem constants
#define BB   2
#define SS   2048
#define DIM  1536
#define NHD  16
#define HD   96
#define NTOK (BB*SS)            // 4096
#define ATT_SCALE 0.10206207261596575f   // 1/sqrt(96)

// Scratch (device globals; allocation-free)
__device__ float g_q[NTOK * DIM];
__device__ float g_k[NTOK * DIM];
__device__ float g_v[NTOK * DIM];

__device__ __half g_h_hi[NTOK * DIM],  g_h_lo[NTOK * DIM];
__device__ __half g_ao_hi[NTOK * DIM];
__device__ __half g_wq_hi[DIM * DIM];
__device__ __half g_wk_hi[DIM * DIM];
__device__ __half g_wv_hi[DIM * DIM];
__device__ __half g_wo_hi[DIM * DIM];

// Post-RoPE fp16 (q split + prescaled by ATT_SCALE; k rounded), f16x2 words
__device__ unsigned int g_qhi[NTOK * DIM / 2], g_qlo[NTOK * DIM / 2];
__device__ unsigned int g_khi[NTOK * DIM / 2];
// V transposed per (b,h): [32][96][2048] fp16 -> words [32][96][1024]
__device__ unsigned int g_vthi[32 * 96 * 1024];

// ---------------------------------------------------------------------------
// helpers
// ---------------------------------------------------------------------------
__device__ __forceinline__ unsigned int pack_f16x2(float lo, float hi) {
    unsigned int r;
    asm("cvt.rn.f16x2.f32 %0, %1, %2;" : "=r"(r) : "f"(hi), "f"(lo));
    return r;
}
__device__ __forceinline__ float f16x2_lo(unsigned int w) {
    float f;
    asm("{ .reg .b16 l, h; mov.b32 {l, h}, %1; cvt.f32.f16 %0, l; }" : "=f"(f) : "r"(w));
    return f;
}
__device__ __forceinline__ float f16x2_hi(unsigned int w) {
    float f;
    asm("{ .reg .b16 l, h; mov.b32 {l, h}, %1; cvt.f32.f16 %0, h; }" : "=f"(f) : "r"(w));
    return f;
}
__device__ __forceinline__ unsigned int smem_u32(const void* p) {
    unsigned int a;
    asm("{ .reg .u64 t; cvta.to.shared.u64 t, %1; cvt.u32.u64 %0, t; }"
        : "=r"(a) : "l"(p));
    return a;
}

#define MMA_F16(d, a, b) \
  asm volatile("mma.sync.aligned.m16n8k16.row.col.f32.f16.f16.f32 " \
    "{%0,%1,%2,%3}, {%4,%5,%6,%7}, {%8,%9}, {%0,%1,%2,%3};" \
    : "+f"(d[0]), "+f"(d[1]), "+f"(d[2]), "+f"(d[3]) \
    : "r"(a[0]), "r"(a[1]), "r"(a[2]), "r"(a[3]), "r"(b[0]), "r"(b[1]))

#define LDSM4(r0, r1, r2, r3, addr) \
  asm volatile("ldmatrix.sync.aligned.m8n8.x4.shared.b16 {%0,%1,%2,%3}, [%4];" \
    : "=r"(r0), "=r"(r1), "=r"(r2), "=r"(r3) : "r"(addr))

#define CPA16(dst_s, src_g) \
  asm volatile("cp.async.ca.shared.global [%0], [%1], 16;" :: "r"(dst_s), "l"(src_g))
#define CPA16CG(dst_s, src_g) \
  asm volatile("cp.async.cg.shared.global [%0], [%1], 16;" :: "r"(dst_s), "l"(src_g))
#define CP_COMMIT() asm volatile("cp.async.commit_group;" ::: "memory")
#define CP_WAIT0()  asm volatile("cp.async.wait_group 0;" ::: "memory")

// ---------------------------------------------------------------------------
// fp32 -> (fp16 hi, fp16 lo) split. n multiple of 4.
// ---------------------------------------------------------------------------
__global__ void __launch_bounds__(256) split_fp16_kernel(
    const float4* __restrict__ x, unsigned int* __restrict__ hi,
    unsigned int* __restrict__ lo, int n4)
{
    int i = blockIdx.x * 256 + threadIdx.x;
    if (i >= n4) return;
    float4 v = x[i];
    unsigned int h0 = pack_f16x2(v.x, v.y);
    unsigned int h1 = pack_f16x2(v.z, v.w);
    unsigned int l0 = pack_f16x2(v.x - f16x2_lo(h0), v.y - f16x2_hi(h0));
    unsigned int l1 = pack_f16x2(v.z - f16x2_lo(h1), v.w - f16x2_hi(h1));
    hi[i*2] = h0; hi[i*2+1] = h1;
    lo[i*2] = l0; lo[i*2+1] = l1;
}

// fp32 -> fp16 round, 4 weight matrices in one launch (grid.z selects)
struct RoundPtrs {
    const float4 *x0, *x1, *x2, *x3;
    unsigned int *o0, *o1, *o2, *o3;
};
__global__ void __launch_bounds__(256) round4_fp16_kernel(RoundPtrs P, int n4)
{
    int i = blockIdx.x * 256 + threadIdx.x;
    if (i >= n4) return;
    int z = blockIdx.y;
    const float4* x = (z == 0) ? P.x0 : (z == 1) ? P.x1 : (z == 2) ? P.x2 : P.x3;
    unsigned int* hi = (z == 0) ? P.o0 : (z == 1) ? P.o1 : (z == 2) ? P.o2 : P.o3;
    float4 v = x[i];
    hi[i*2]   = pack_f16x2(v.x, v.y);
    hi[i*2+1] = pack_f16x2(v.z, v.w);
}

// ---------------------------------------------------------------------------
// ldmatrix tensor-core GEMM: C[m][n] = sum_k A[m][k] * W[n][k]
// CTA 128x128, BK=64, 256 threads, warp 64x32. split_mask bit z: A split hi+lo
// (2 MMAs) vs hi-only (1 MMA). grid.z = QKV fusion.
// ---------------------------------------------------------------------------
#define GL_STAGE 49152     // 3 tiles x 128 rows x 128B (Ahi, Alo, Bhi)
#define GL_SMEM  (2 * GL_STAGE)
#define GL_NC    (DIM / 64)   // 24

struct GemmPtrs {
    const __half *b0, *b1, *b2;
    float *c0, *c1, *c2;
    int split_mask;
};

__device__ __forceinline__ void gl_prefetch(
    unsigned int stage_base,
    const __half* __restrict__ a_h, const __half* __restrict__ a_l,
    const __half* __restrict__ b_h,
    int tid, int koff, bool with_lo)
{
    #pragma unroll
    for (int t = 0; t < 3; t++) {
        if (t == 1 && !with_lo) continue;
        const __half* s = (t == 0) ? a_h : (t == 1) ? a_l : b_h;
        #pragma unroll
        for (int i = 0; i < 4; i++) {
            int w = tid + 256 * i;          // 0..1023
            int r = w >> 3, cc = w & 7;     // row, 16B chunk
            unsigned int off = r * 128 + cc * 16;
            unsigned int dst = stage_base + t * 16384 + (off ^ ((off >> 3) & 0x70));
            CPA16CG(dst, s + (size_t)r * DIM + koff + cc * 8);
        }
    }
    CP_COMMIT();
}

__global__ void __launch_bounds__(256, 2) gemm_ldsm_nt(
    const __half* __restrict__ Ahi, const __half* __restrict__ Alo,
    GemmPtrs P)
{
    extern __shared__ char smraw[];
    const unsigned int sbase = smem_u32(smraw);
    const int tid  = threadIdx.x;
    const int lane = tid & 31;
    const int warp = tid >> 5;
    const int warp_m = warp >> 2;    // 0..1
    const int warp_n = warp & 3;     // 0..3
    const int row0 = blockIdx.y * 128;
    const int col0 = blockIdx.x * 128;
    const int z = blockIdx.z;
    const bool use_lo = (P.split_mask >> z) & 1;

    const __half* Whi = (z == 0) ? P.b0 : (z == 1) ? P.b1 : P.b2;
    float* C = (z == 0) ? P.c0 : (z == 1) ? P.c1 : P.c2;

    const __half* a_h = Ahi + (size_t)row0 * DIM;
    const __half* a_l = Alo + (size_t)row0 * DIM;
    const __half* b_h = Whi + (size_t)col0 * DIM;

    // ldmatrix lane address components
    const int g = lane >> 3, j = lane & 7;
    const unsigned int rA = warp_m * 64 + (g & 1) * 8 + j;   // + mbl*16
    const unsigned int cA = (g >> 1) * 16;                   // + kc*32
    const unsigned int rB = warp_n * 32 + (g >> 1) * 8 + j;  // + nb2*16
    const unsigned int cB = (g & 1) * 16;

    float acc[4][4][4] = {};    // [mbl][nbl][reg]

    gl_prefetch(sbase, a_h, a_l, b_h, tid, 0, use_lo);

    for (int c = 0; c < GL_NC; c++) {
        CP_WAIT0();
        __syncthreads();
        if (c + 1 < GL_NC)
            gl_prefetch(sbase + ((c + 1) & 1) * GL_STAGE, a_h, a_l, b_h,
                        tid, (c + 1) * 64, use_lo);

        const unsigned int stb = sbase + (c & 1) * GL_STAGE;

        #pragma unroll
        for (int kc = 0; kc < 4; kc++) {
            unsigned int ah[4][4], al[4][4];
            #pragma unroll
            for (int mbl = 0; mbl < 4; mbl++) {
                unsigned int off = (rA + mbl * 16) * 128 + cA + kc * 32;
                unsigned int sw = off ^ ((off >> 3) & 0x70);
                LDSM4(ah[mbl][0], ah[mbl][1], ah[mbl][2], ah[mbl][3], stb + sw);
                if (use_lo)
                    LDSM4(al[mbl][0], al[mbl][1], al[mbl][2], al[mbl][3],
                          stb + 16384 + sw);
            }
            unsigned int bh[4][2];
            #pragma unroll
            for (int nb2 = 0; nb2 < 2; nb2++) {
                unsigned int off = (rB + nb2 * 16) * 128 + cB + kc * 32;
                unsigned int sw = off ^ ((off >> 3) & 0x70);
                unsigned int r0, r1, r2, r3;
                LDSM4(r0, r1, r2, r3, stb + 32768 + sw);
                bh[2*nb2][0] = r0; bh[2*nb2][1] = r1;
                bh[2*nb2+1][0] = r2; bh[2*nb2+1][1] = r3;
            }
            #pragma unroll
            for (int mbl = 0; mbl < 4; mbl++)
                #pragma unroll
                for (int nbl = 0; nbl < 4; nbl++) {
                    MMA_F16(acc[mbl][nbl], ah[mbl], bh[nbl]);       // hi*B
                    if (use_lo)
                        MMA_F16(acc[mbl][nbl], al[mbl], bh[nbl]);   // lo*B
                }
        }
    }

    #pragma unroll
    for (int mbl = 0; mbl < 4; mbl++) {
        int mrow = row0 + warp_m * 64 + mbl * 16 + (lane >> 2);
        #pragma unroll
        for (int nbl = 0; nbl < 4; nbl++) {
            int ncol = col0 + warp_n * 32 + nbl * 8 + (lane & 3) * 2;
            float2 v0 = make_float2(acc[mbl][nbl][0], acc[mbl][nbl][1]);
            float2 v1 = make_float2(acc[mbl][nbl][2], acc[mbl][nbl][3]);
            *(float2*)&C[(size_t)mrow * DIM + ncol]       = v0;
            *(float2*)&C[(size_t)(mrow + 8) * DIM + ncol] = v1;
        }
    }
}

// ---------------------------------------------------------------------------
// RoPE + fp16: q split (hi/lo, prescaled), k rounded -> f16x2 words.
// ---------------------------------------------------------------------------
__global__ void __launch_bounds__(256) rope_split_kernel(
    const float* __restrict__ q, const float* __restrict__ k,
    const int* __restrict__ xyz,
    unsigned int* __restrict__ qhi, unsigned int* __restrict__ qlo,
    unsigned int* __restrict__ khi)
{
    int idx = blockIdx.x * 256 + threadIdx.x;   // NTOK*16*3*8
    int j2 = idx & 7;
    int p  = (idx >> 3) % 3;
    int th = idx / 24;
    int h  = th & 15;
    int t  = th >> 4;
    if (t >= NTOK) return;

    float pos = (float)xyz[t * 3 + p];
    const float c = 0.83048202372184058696f;   // log2(10000)/16
    int j0 = 2 * j2;
    float s0, c0, s1, c1;
    sincosf(pos * exp2f(-(float)j0 * c), &s0, &c0);
    sincosf(pos * exp2f(-(float)(j0 + 1) * c), &s1, &c1);

    int base = t * DIM + h * HD + p * 32 + j0;
    int wbase = t * (DIM/2) + h * (HD/2) + p * 16 + j2;

    {
        float2 a = *(const float2*)&q[base];
        float2 b = *(const float2*)&q[base + 16];
        float o1x = (a.x * c0 - b.x * s0) * ATT_SCALE;
        float o1y = (a.y * c1 - b.y * s1) * ATT_SCALE;
        float o2x = (b.x * c0 + a.x * s0) * ATT_SCALE;
        float o2y = (b.y * c1 + a.y * s1) * ATT_SCALE;
        unsigned int h1 = pack_f16x2(o1x, o1y);
        unsigned int h2 = pack_f16x2(o2x, o2y);
        unsigned int l1 = pack_f16x2(o1x - f16x2_lo(h1), o1y - f16x2_hi(h1));
        unsigned int l2 = pack_f16x2(o2x - f16x2_lo(h2), o2y - f16x2_hi(h2));
        qhi[wbase] = h1; qhi[wbase + 8] = h2;
        qlo[wbase] = l1; qlo[wbase + 8] = l2;
    }
    {
        float2 a = *(const float2*)&k[base];
        float2 b = *(const float2*)&k[base + 16];
        float o1x = a.x * c0 - b.x * s0;
        float o1y = a.y * c1 - b.y * s1;
        float o2x = b.x * c0 + a.x * s0;
        float o2y = b.y * c1 + a.y * s1;
        khi[wbase]     = pack_f16x2(o1x, o1y);
        khi[wbase + 8] = pack_f16x2(o2x, o2y);
    }
}

// ---------------------------------------------------------------------------
// V transpose + fp16 round
// ---------------------------------------------------------------------------
__global__ void __launch_bounds__(128) vtrans_kernel(
    const float* __restrict__ v, unsigned int* __restrict__ vthi)
{
    __shared__ float sm[96 * 65];
    const int tid = threadIdx.x;
    const int bh = blockIdx.y;
    const int b = bh >> 4, h = bh & 15;
    const int s0 = blockIdx.x * 64;

    {
        int s = tid >> 1, half = tid & 1;
        const float* src = v + (size_t)(b * SS + s0 + s) * DIM + h * HD + half * 48;
        #pragma unroll
        for (int i = 0; i < 12; i++) {
            float4 x = *(const float4*)(src + i * 4);
            int d = half * 48 + i * 4;
            sm[(d + 0) * 65 + s] = x.x;
            sm[(d + 1) * 65 + s] = x.y;
            sm[(d + 2) * 65 + s] = x.z;
            sm[(d + 3) * 65 + s] = x.w;
        }
    }
    __syncthreads();

    #pragma unroll
    for (int i = 0; i < 24; i++) {
        int w = tid + 128 * i;
        int d = w >> 5, j = w & 31;
        float f0 = sm[d * 65 + 2 * j];
        float f1 = sm[d * 65 + 2 * j + 1];
        vthi[(size_t)(bh * 96 + d) * 1024 + (s0 >> 1) + j] = pack_f16x2(f0, f1);
    }
}

// ---------------------------------------------------------------------------
// MMA flash attention (fp16: Q split; K/V/P rounded). Output: aohi only.
// Smem/buffer: KHI [64][52] words, VHI [96][36] words.
// ---------------------------------------------------------------------------
#define AKHI 0
#define AVHI 3328
#define ABUF 6784
#define ATT_SMEM_BYTES (2 * ABUF * 4)

__global__ void __launch_bounds__(128, 2) attn_mma_kernel(
    const unsigned int* __restrict__ qhi, const unsigned int* __restrict__ qlo,
    const unsigned int* __restrict__ khi,
    const unsigned int* __restrict__ vthi,
    unsigned int* __restrict__ aohi)
{
    extern __shared__ unsigned int smw[];
    unsigned int sbase = smem_u32(smw);

    const int tid  = threadIdx.x;
    const int lane = tid & 31;
    const int warp = tid >> 5;
    const int qt = blockIdx.x;
    const int bh = blockIdx.y;
    const int b = bh >> 4, h = bh & 15;
    const int h48 = h * 48;
    const int qrow0 = b * SS + qt * 64;

    unsigned int qh[6][4], ql[6][4];
    {
        const unsigned int* qhg = qhi + (size_t)qrow0 * 768 + h48;
        const unsigned int* qlg = qlo + (size_t)qrow0 * 768 + h48;
        int r0 = warp * 16 + (lane >> 2);
        #pragma unroll
        for (int kb = 0; kb < 6; kb++) {
            int w0 = kb * 8 + (lane & 3);
            qh[kb][0] = qhg[(size_t)r0 * 768 + w0];
            qh[kb][1] = qhg[(size_t)(r0 + 8) * 768 + w0];
            qh[kb][2] = qhg[(size_t)r0 * 768 + w0 + 4];
            qh[kb][3] = qhg[(size_t)(r0 + 8) * 768 + w0 + 4];
            ql[kb][0] = qlg[(size_t)r0 * 768 + w0];
            ql[kb][1] = qlg[(size_t)(r0 + 8) * 768 + w0];
            ql[kb][2] = qlg[(size_t)r0 * 768 + w0 + 4];
            ql[kb][3] = qlg[(size_t)(r0 + 8) * 768 + w0 + 4];
        }
    }

    float O[12][4];
    #pragma unroll
    for (int nb = 0; nb < 12; nb++)
        #pragma unroll
        for (int i = 0; i < 4; i++) O[nb][i] = 0.0f;
    float m0 = -CUDART_INF_F, m1 = -CUDART_INF_F, l0 = 0.0f, l1 = 0.0f;

#define PREFETCH(bi, ktv)                                                      \
    {                                                                          \
        int ktok = b * SS + (ktv) * 64;                                        \
        _Pragma("unroll")                                                      \
        for (int i = 0; i < 6; i++) {                                          \
            int cc = tid + 128 * i;                                            \
            int key = cc / 12, j = cc - key * 12;                              \
            unsigned int dw = ((bi) * ABUF + key * 52 + j * 4);                \
            CPA16(sbase + dw * 4,                                              \
                  khi + (size_t)(ktok + key) * 768 + h48 + j * 4);             \
        }                                                                      \
        _Pragma("unroll")                                                      \
        for (int i = 0; i < 6; i++) {                                          \
            int cc = tid + 128 * i;                                            \
            int d = cc >> 3, j = cc & 7;                                       \
            unsigned int dw = ((bi) * ABUF + AVHI + d * 36 + j * 4);           \
            CPA16(sbase + dw * 4,                                              \
                  vthi + (size_t)(bh * 96 + d) * 1024 + (ktv) * 32 + j * 4);   \
        }                                                                      \
        CP_COMMIT();                                                           \
    }

    PREFETCH(0, 0);

    for (int kt = 0; kt < SS / 64; kt++) {
        CP_WAIT0();
        __syncthreads();
        if (kt + 1 < SS / 64) PREFETCH((kt + 1) & 1, kt + 1);

        const unsigned int* kh = smw + (kt & 1) * ABUF + AKHI;
        const unsigned int* vh = smw + (kt & 1) * ABUF + AVHI;

        float S[8][4];
        #pragma unroll
        for (int nb = 0; nb < 8; nb++) {
            #pragma unroll
            for (int i = 0; i < 4; i++) S[nb][i] = 0.0f;
            int key = nb * 8 + (lane >> 2);
            #pragma unroll
            for (int kb = 0; kb < 6; kb++) {
                int w0 = kb * 8 + (lane & 3);
                unsigned int bhf[2] = { kh[key * 52 + w0], kh[key * 52 + w0 + 4] };
                MMA_F16(S[nb], qh[kb], bhf);
                MMA_F16(S[nb], ql[kb], bhf);
            }
        }

        float ml0 = -CUDART_INF_F, ml1 = -CUDART_INF_F;
        #pragma unroll
        for (int nb = 0; nb < 8; nb++) {
            ml0 = fmaxf(ml0, fmaxf(S[nb][0], S[nb][1]));
            ml1 = fmaxf(ml1, fmaxf(S[nb][2], S[nb][3]));
        }
        ml0 = fmaxf(ml0, __shfl_xor_sync(0xffffffffu, ml0, 1));
        ml0 = fmaxf(ml0, __shfl_xor_sync(0xffffffffu, ml0, 2));
        ml1 = fmaxf(ml1, __shfl_xor_sync(0xffffffffu, ml1, 1));
        ml1 = fmaxf(ml1, __shfl_xor_sync(0xffffffffu, ml1, 2));
        float mn0 = fmaxf(m0, ml0), mn1 = fmaxf(m1, ml1);
        float sc0 = __expf(m0 - mn0), sc1 = __expf(m1 - mn1);
        float r0 = 0.0f, r1 = 0.0f;
        #pragma unroll
        for (int nb = 0; nb < 8; nb++) {
            S[nb][0] = __expf(S[nb][0] - mn0);
            S[nb][1] = __expf(S[nb][1] - mn0);
            S[nb][2] = __expf(S[nb][2] - mn1);
            S[nb][3] = __expf(S[nb][3] - mn1);
            r0 += S[nb][0] + S[nb][1];
            r1 += S[nb][2] + S[nb][3];
        }
        r0 += __shfl_xor_sync(0xffffffffu, r0, 1);
        r0 += __shfl_xor_sync(0xffffffffu, r0, 2);
        r1 += __shfl_xor_sync(0xffffffffu, r1, 1);
        r1 += __shfl_xor_sync(0xffffffffu, r1, 2);
        l0 = l0 * sc0 + r0;  m0 = mn0;
        l1 = l1 * sc1 + r1;  m1 = mn1;

        #pragma unroll
        for (int nb = 0; nb < 12; nb++) {
            O[nb][0] *= sc0; O[nb][1] *= sc0;
            O[nb][2] *= sc1; O[nb][3] *= sc1;
        }

        // P: C-frag -> fp16 A-frag (hi only; P in [0,1], rounding ~1e-4 of sum)
        unsigned int ph[4][4];
        #pragma unroll
        for (int kb = 0; kb < 4; kb++) {
            float f[8] = { S[2*kb][0], S[2*kb][1], S[2*kb][2], S[2*kb][3],
                           S[2*kb+1][0], S[2*kb+1][1], S[2*kb+1][2], S[2*kb+1][3] };
            #pragma unroll
            for (int rgp = 0; rgp < 4; rgp++)
                ph[kb][rgp] = pack_f16x2(f[2*rgp], f[2*rgp+1]);
        }

        #pragma unroll
        for (int nb = 0; nb < 12; nb++) {
            int d = nb * 8 + (lane >> 2);
            #pragma unroll
            for (int kb = 0; kb < 4; kb++) {
                int w0 = kb * 8 + (lane & 3);
                unsigned int bhf[2] = { vh[d * 36 + w0], vh[d * 36 + w0 + 4] };
                MMA_F16(O[nb], ph[kb], bhf);
            }
        }
    }

    float li0 = 1.0f / l0, li1 = 1.0f / l1;
    int tok0 = qrow0 + warp * 16 + (lane >> 2);
    int tok1 = tok0 + 8;
    #pragma unroll
    for (int nb = 0; nb < 12; nb++) {
        int wd = nb * 4 + (lane & 3);
        aohi[(size_t)tok0 * 768 + h48 + wd] =
            pack_f16x2(O[nb][0] * li0, O[nb][1] * li0);
        aohi[(size_t)tok1 * 768 + h48 + wd] =
            pack_f16x2(O[nb][2] * li1, O[nb][3] * li1);
    }
}

// ---------------------------------------------------------------------------
extern "C" void kernel_launch(void* const* d_in, const int* in_sizes, int n_in,
                              void* d_out, int out_size)
{
    const int*   xyz = (const int*)d_in[0];
    const float* h   = (const float*)d_in[1];
    const float* wq  = (const float*)d_in[2];
    const float* wk  = (const float*)d_in[3];
    const float* wv  = (const float*)d_in[4];
    const float* wo  = (const float*)d_in[5];
    float* out = (float*)d_out;

    float *pq, *pk, *pv;
    cudaGetSymbolAddress((void**)&pq,  g_q);
    cudaGetSymbolAddress((void**)&pk,  g_k);
    cudaGetSymbolAddress((void**)&pv,  g_v);

    __half *hh, *hl, *aoh, *wqh, *wkh, *wvh, *woh;
    cudaGetSymbolAddress((void**)&hh,  g_h_hi);  cudaGetSymbolAddress((void**)&hl,  g_h_lo);
    cudaGetSymbolAddress((void**)&aoh, g_ao_hi);
    cudaGetSymbolAddress((void**)&wqh, g_wq_hi);
    cudaGetSymbolAddress((void**)&wkh, g_wk_hi);
    cudaGetSymbolAddress((void**)&wvh, g_wv_hi);
    cudaGetSymbolAddress((void**)&woh, g_wo_hi);

    unsigned int *uqh, *uql, *ukh, *uvh;
    cudaGetSymbolAddress((void**)&uqh, g_qhi);  cudaGetSymbolAddress((void**)&uql, g_qlo);
    cudaGetSymbolAddress((void**)&ukh, g_khi);
    cudaGetSymbolAddress((void**)&uvh, g_vthi);

    const int nH4 = NTOK * DIM / 4;
    const int nW4 = DIM * DIM / 4;
    split_fp16_kernel<<<(nH4 + 255)/256, 256>>>((const float4*)h,
        (unsigned int*)hh, (unsigned int*)hl, nH4);

    RoundPtrs Rp;
    Rp.x0 = (const float4*)wq; Rp.o0 = (unsigned int*)wqh;
    Rp.x1 = (const float4*)wk; Rp.o1 = (unsigned int*)wkh;
    Rp.x2 = (const float4*)wv; Rp.o2 = (unsigned int*)wvh;
    Rp.x3 = (const float4*)wo; Rp.o3 = (unsigned int*)woh;
    dim3 rg((nW4 + 255)/256, 4);
    round4_fp16_kernel<<<rg, 256>>>(Rp, nW4);

    cudaFuncSetAttribute(gemm_ldsm_nt, cudaFuncAttributeMaxDynamicSharedMemorySize, GL_SMEM);

    // fused QKV projections: Q split (bit0), K/V hi-only
    GemmPtrs Pqkv;
    Pqkv.b0 = wqh; Pqkv.b1 = wkh; Pqkv.b2 = wvh;
    Pqkv.c0 = pq;  Pqkv.c1 = pk;  Pqkv.c2 = pv;
    Pqkv.split_mask = 0x1;
    dim3 gq(DIM / 128, NTOK / 128, 3);   // (12, 32, 3)
    gemm_ldsm_nt<<<gq, 256, GL_SMEM>>>(hh, hl, Pqkv);

    int rope_threads = NTOK * NHD * 3 * 8;
    rope_split_kernel<<<rope_threads / 256, 256>>>(pq, pk, xyz, uqh, uql, ukh);

    dim3 vgrid(SS / 64, BB * NHD);
    vtrans_kernel<<<vgrid, 128>>>(pv, uvh);

    cudaFuncSetAttribute(attn_mma_kernel, cudaFuncAttributeMaxDynamicSharedMemorySize, ATT_SMEM_BYTES);
    dim3 agrid(SS / 64, BB * NHD);
    attn_mma_kernel<<<agrid, 128, ATT_SMEM_BYTES>>>(
        uqh, uql, ukh, uvh, (unsigned int*)aoh);

    // O projection: ao rounded (hi-only, 1 MMA)
    GemmPtrs Po;
    Po.b0 = woh; Po.b1 = woh; Po.b2 = woh;
    Po.c0 = out; Po.c1 = out; Po.c2 = out;
    Po.split_mask = 0x0;
    dim3 go(DIM / 128, NTOK / 128, 1);
    gemm_ldsm_nt<<<go, 256, GL_SMEM>>>(aoh, aoh, Po);
}